// round 10
// baseline (speedup 1.0000x reference)
#include <cuda_runtime.h>
#include <cuda_bf16.h>
#include <math.h>

#define NB 8
#define NN 2048
#define ND 128
#define NT2 32                    // 64-row q-tiles

// ---------------- scratch (allocation-free device globals) ----------------
__device__ __align__(16) unsigned short g_h1hi[NB * NN * ND];  // bf16 hi of h1 [b,n,d]
__device__ __align__(16) unsigned short g_h1lo[NB * NN * ND];  // bf16 lo (residual)
__device__ __align__(16) float g_rinv[NB * NN];
__device__ __align__(16) float g_agg[NB * NN * ND];            // inter-layer fp32 (pre-relu)

// ---------------- helpers ----------------
__device__ __forceinline__ unsigned smem_u32(const void* p) {
    unsigned a;
    asm("{ .reg .u64 t; cvta.to.shared.u64 t, %1; cvt.u32.u64 %0, t; }" : "=r"(a) : "l"(p));
    return a;
}
__device__ __forceinline__ void ldmx4(unsigned* r, unsigned a) {
    asm volatile("ldmatrix.sync.aligned.m8n8.x4.shared.b16 {%0,%1,%2,%3}, [%4];"
        : "=r"(r[0]), "=r"(r[1]), "=r"(r[2]), "=r"(r[3]) : "r"(a));
}
__device__ __forceinline__ void ldmx4t(unsigned* r, unsigned a) {
    asm volatile("ldmatrix.sync.aligned.m8n8.x4.trans.shared.b16 {%0,%1,%2,%3}, [%4];"
        : "=r"(r[0]), "=r"(r[1]), "=r"(r[2]), "=r"(r[3]) : "r"(a));
}
__device__ __forceinline__ void mma_bf16(float* d, const unsigned* a,
                                         unsigned b0, unsigned b1) {
    asm volatile("mma.sync.aligned.m16n8k16.row.col.f32.bf16.bf16.f32 "
        "{%0,%1,%2,%3},{%4,%5,%6,%7},{%8,%9},{%0,%1,%2,%3};"
        : "+f"(d[0]), "+f"(d[1]), "+f"(d[2]), "+f"(d[3])
        : "r"(a[0]), "r"(a[1]), "r"(a[2]), "r"(a[3]), "r"(b0), "r"(b1));
}
__device__ __forceinline__ unsigned pack_bf16(float lo, float hi) {
    unsigned r;
    asm("cvt.rn.bf16x2.f32 %0, %1, %2;" : "=r"(r) : "f"(hi), "f"(lo));
    return r;
}
#define CP_ASYNC16(dst, src) \
    asm volatile("cp.async.cg.shared.global [%0], [%1], 16;" \
        :: "r"((unsigned)(dst)), "l"(src) : "memory")
#define CP_COMMIT() asm volatile("cp.async.commit_group;" ::: "memory")
#define CP_WAIT0()  asm volatile("cp.async.wait_group 0;" ::: "memory")

// ============================================================
// klinear: h1 = relu?(hin) @ W + b ; rinv = 1/max(||h1||,eps)
// ============================================================
__global__ __launch_bounds__(256) void klinear(
    const float* __restrict__ xin, const float* __restrict__ W,
    const float* __restrict__ bias, int use_gagg)
{
    __shared__ float sH[64][128];
    const float* hin = use_gagg ? (const float*)g_agg : xin;
    int tid = threadIdx.x;
    size_t row0 = (size_t)blockIdx.x * 64;

#pragma unroll
    for (int i = tid; i < 64 * 32; i += 256) {
        int r = i >> 5, kb = i & 31;
        float4 v = *(const float4*)(hin + (row0 + r) * (size_t)ND + 4 * kb);
        if (use_gagg) {
            v.x = fmaxf(v.x, 0.0f); v.y = fmaxf(v.y, 0.0f);
            v.z = fmaxf(v.z, 0.0f); v.w = fmaxf(v.w, 0.0f);
        }
        *(float4*)&sH[r][4 * kb] = v;
    }
    __syncthreads();

    int wy = tid >> 5, tx = tid & 31;   // warp wy: rows 8*wy..8*wy+7
    float acc[8][4];
    {
        float4 bv = *(const float4*)(bias + 4 * tx);
#pragma unroll
        for (int i = 0; i < 8; i++) {
            acc[i][0] = bv.x; acc[i][1] = bv.y; acc[i][2] = bv.z; acc[i][3] = bv.w;
        }
    }
#pragma unroll 4
    for (int k = 0; k < ND; k++) {
        float4 wv = *(const float4*)(W + (size_t)k * ND + 4 * tx);
#pragma unroll
        for (int i = 0; i < 8; i++) {
            float hr = sH[8 * wy + i][k];
            acc[i][0] = fmaf(hr, wv.x, acc[i][0]);
            acc[i][1] = fmaf(hr, wv.y, acc[i][1]);
            acc[i][2] = fmaf(hr, wv.z, acc[i][2]);
            acc[i][3] = fmaf(hr, wv.w, acc[i][3]);
        }
    }

#pragma unroll
    for (int i = 0; i < 8; i++) {
        float ss = acc[i][0] * acc[i][0] + acc[i][1] * acc[i][1]
                 + acc[i][2] * acc[i][2] + acc[i][3] * acc[i][3];
#pragma unroll
        for (int o = 16; o > 0; o >>= 1) ss += __shfl_xor_sync(0xffffffffu, ss, o);
        float ri = 1.0f / fmaxf(sqrtf(ss), 1e-12f);
        size_t row = row0 + 8 * wy + i;
        unsigned short ush[4], usl[4];
#pragma unroll
        for (int c2 = 0; c2 < 4; c2++) {
            __nv_bfloat16 hb = __float2bfloat16(acc[i][c2]);
            float res = acc[i][c2] - __bfloat162float(hb);
            ush[c2] = __bfloat16_as_ushort(hb);
            usl[c2] = __bfloat16_as_ushort(__float2bfloat16(res));
        }
        uint2 ph = make_uint2(ush[0] | ((unsigned)ush[1] << 16), ush[2] | ((unsigned)ush[3] << 16));
        uint2 pl = make_uint2(usl[0] | ((unsigned)usl[1] << 16), usl[2] | ((unsigned)usl[3] << 16));
        *(uint2*)(g_h1hi + row * ND + 4 * tx) = ph;
        *(uint2*)(g_h1lo + row * ND + 4 * tx) = pl;
        if (tx == 0) g_rinv[row] = ri;
    }
}

// ============================================================
// kaggr_mma: 64-row p/q tiles, 128 threads (4 warps), 2 CTAs/SM.
// out[p,:] = sum_q ew[p,q]*rp*rq*(h1_p . h1_q) * h1[q,:]
// ============================================================
#define SROWB 272                 // bytes per smem row (128+8 halfs)
#define TIL64 17408               // one 64-row tile (hi or lo)
#define OFF_HPH 0
#define OFF_HPL TIL64
#define OFF_HQ0 (2 * TIL64)       // buffer 0: hi, lo at +TIL64
#define OFF_HQ1 (4 * TIL64)       // buffer 1
#define OFF_RQ  (6 * TIL64)       // 2 x 256B
#define SM_TOT  (6 * TIL64 + 512)

__global__ __launch_bounds__(128, 2) void kaggr_mma(
    const float* __restrict__ ew, float* __restrict__ dout, int is_last)
{
    extern __shared__ char sm[];
    unsigned sb = smem_u32(sm);
    int tid = threadIdx.x, wid = tid >> 5, lane = tid & 31;
    int b = blockIdx.y, p0 = blockIdx.x * 64;

    const unsigned short* hh = g_h1hi + (size_t)b * NN * ND;
    const unsigned short* hl = g_h1lo + (size_t)b * NN * ND;
    const float* ewb = ew + (size_t)b * NN * NN;
    const float* rb = g_rinv + (size_t)b * NN;
    float* ob = (is_last ? dout : (float*)g_agg) + (size_t)b * NN * ND;

    // persistent Hp hi/lo tile (64 rows)
#pragma unroll
    for (int f = tid; f < 1024; f += 128) {
        int r = f >> 4, ch = f & 15;
        *(uint4*)(sm + OFF_HPH + r * SROWB + ch * 16) =
            *(const uint4*)(hh + (size_t)(p0 + r) * ND + ch * 8);
        *(uint4*)(sm + OFF_HPL + r * SROWB + ch * 16) =
            *(const uint4*)(hl + (size_t)(p0 + r) * ND + ch * 8);
    }

    int g = lane >> 2, c = lane & 3;
    int mrow = wid * 16;
    float rp0 = rb[p0 + mrow + g];
    float rp1 = rb[p0 + mrow + g + 8];
    const float* ew0 = ewb + (size_t)(p0 + mrow + g) * NN;
    const float* ew1 = ewb + (size_t)(p0 + mrow + g + 8) * NN;

    int grp = lane >> 3, wi = lane & 7;
    unsigned offA = (unsigned)((mrow + wi + (grp & 1) * 8) * SROWB + (grp >> 1) * 16);
    unsigned offB = (unsigned)((wi + (grp >> 1) * 8) * SROWB + (grp & 1) * 16);
    unsigned offT = (unsigned)((wi + (grp & 1) * 8) * SROWB + (grp >> 1) * 16);

    float o[16][4];
#pragma unroll
    for (int j = 0; j < 16; j++)
#pragma unroll
        for (int k = 0; k < 4; k++) o[j][k] = 0.0f;

    auto issue_tile = [&](int t, unsigned bufoff) {
        int q0 = t << 6;
#pragma unroll
        for (int f = tid; f < 1024; f += 128) {
            int r = f >> 4, ch = f & 15;
            CP_ASYNC16(sb + bufoff + r * SROWB + ch * 16,
                       hh + (size_t)(q0 + r) * ND + ch * 8);
            CP_ASYNC16(sb + bufoff + TIL64 + r * SROWB + ch * 16,
                       hl + (size_t)(q0 + r) * ND + ch * 8);
        }
        if (tid < 16) CP_ASYNC16(sb + OFF_RQ + ((unsigned)(t & 1) << 8) + tid * 16,
                                 rb + q0 + tid * 4);
        CP_COMMIT();
    };

    issue_tile(0, OFF_HQ0);

    for (int t = 0; t < NT2; t++) {
        unsigned bufoff = (t & 1) ? OFF_HQ1 : OFF_HQ0;
        CP_WAIT0();
        __syncthreads();
        if (t + 1 < NT2) issue_tile(t + 1, (t & 1) ? OFF_HQ0 : OFF_HQ1);

        int q0 = t << 6;
        const float* s_rq = (const float*)(sm + OFF_RQ + ((unsigned)(t & 1) << 8));

        // EW prefetch for this tile (hidden under GEMM1 MMAs)
        float2 eq0[8], eq1[8];
#pragma unroll
        for (int tl = 0; tl < 8; tl++) {
            int col = q0 + tl * 8 + 2 * c;
            eq0[tl] = *(const float2*)(ew0 + col);
            eq1[tl] = *(const float2*)(ew1 + col);
        }

        // ---- GEMM1: S = Hp . Hq^T (64 q-cols, 3-pass split) ----
        float s[8][4];
#pragma unroll
        for (int j = 0; j < 8; j++)
#pragma unroll
            for (int k = 0; k < 4; k++) s[j][k] = 0.0f;

#pragma unroll
        for (int kk = 0; kk < 8; kk++) {
            unsigned ah[4], al[4];
            ldmx4(ah, sb + OFF_HPH + offA + kk * 32);
            ldmx4(al, sb + OFF_HPL + offA + kk * 32);
            unsigned bh[4][4], bl[4][4];
#pragma unroll
            for (int np = 0; np < 4; np++) {
                unsigned nb = bufoff + (unsigned)(np * 16 * SROWB);
                ldmx4(bh[np], sb + nb + offB + kk * 32);
                ldmx4(bl[np], sb + nb + TIL64 + offB + kk * 32);
            }
#pragma unroll
            for (int np = 0; np < 4; np++) {   // pass 1: hi*hi
                mma_bf16(s[2 * np], ah, bh[np][0], bh[np][1]);
                mma_bf16(s[2 * np + 1], ah, bh[np][2], bh[np][3]);
            }
#pragma unroll
            for (int np = 0; np < 4; np++) {   // pass 2: lo*hi
                mma_bf16(s[2 * np], al, bh[np][0], bh[np][1]);
                mma_bf16(s[2 * np + 1], al, bh[np][2], bh[np][3]);
            }
#pragma unroll
            for (int np = 0; np < 4; np++) {   // pass 3: hi*lo
                mma_bf16(s[2 * np], ah, bl[np][0], bl[np][1]);
                mma_bf16(s[2 * np + 1], ah, bl[np][2], bl[np][3]);
            }
        }

        // ---- scale + bf16 split -> A fragments (4 kl groups of k16) ----
        unsigned SAh[4][4], SAl[4][4];
#pragma unroll
        for (int tl = 0; tl < 8; tl++) {
            int col = tl * 8 + 2 * c;
            float2 rq2 = *(const float2*)&s_rq[col];
            float2 e0 = eq0[tl];
            float2 e1 = eq1[tl];
            float v0 = s[tl][0] * (rp0 * rq2.x * e0.x);
            float v1 = s[tl][1] * (rp0 * rq2.y * e0.y);
            float v2 = s[tl][2] * (rp1 * rq2.x * e1.x);
            float v3 = s[tl][3] * (rp1 * rq2.y * e1.y);
            __nv_bfloat16 h0 = __float2bfloat16(v0);
            __nv_bfloat16 h1v = __float2bfloat16(v1);
            __nv_bfloat16 h2 = __float2bfloat16(v2);
            __nv_bfloat16 h3 = __float2bfloat16(v3);
            float r0v = v0 - __bfloat162float(h0);
            float r1v = v1 - __bfloat162float(h1v);
            float r2v = v2 - __bfloat162float(h2);
            float r3v = v3 - __bfloat162float(h3);
            int kl = tl >> 1, sl = (tl & 1) * 2;
            SAh[kl][sl]     = (unsigned)__bfloat16_as_ushort(h0)
                            | ((unsigned)__bfloat16_as_ushort(h1v) << 16);
            SAh[kl][sl + 1] = (unsigned)__bfloat16_as_ushort(h2)
                            | ((unsigned)__bfloat16_as_ushort(h3) << 16);
            SAl[kl][sl]     = pack_bf16(r0v, r1v);
            SAl[kl][sl + 1] = pack_bf16(r2v, r3v);
        }

        // ---- GEMM2: o += S x Hq (contraction over 64 q-rows) ----
#pragma unroll
        for (int kl = 0; kl < 4; kl++) {
            unsigned kb = bufoff + (unsigned)(kl * 16 * SROWB);
#pragma unroll
            for (int npg = 0; npg < 2; npg++) {
                unsigned bh[4][4], bl[4][4];
#pragma unroll
                for (int np = 0; np < 4; np++) {
                    ldmx4t(bh[np], sb + kb + offT + (npg * 4 + np) * 32);
                    ldmx4t(bl[np], sb + kb + TIL64 + offT + (npg * 4 + np) * 32);
                }
#pragma unroll
                for (int np = 0; np < 4; np++) {   // pass 1: SAh * bh
                    int j = (npg * 4 + np) * 2;
                    mma_bf16(o[j], SAh[kl], bh[np][0], bh[np][1]);
                    mma_bf16(o[j + 1], SAh[kl], bh[np][2], bh[np][3]);
                }
#pragma unroll
                for (int np = 0; np < 4; np++) {   // pass 2: SAl * bh
                    int j = (npg * 4 + np) * 2;
                    mma_bf16(o[j], SAl[kl], bh[np][0], bh[np][1]);
                    mma_bf16(o[j + 1], SAl[kl], bh[np][2], bh[np][3]);
                }
#pragma unroll
                for (int np = 0; np < 4; np++) {   // pass 3: SAh * bl
                    int j = (npg * 4 + np) * 2;
                    mma_bf16(o[j], SAh[kl], bl[np][0], bl[np][1]);
                    mma_bf16(o[j + 1], SAh[kl], bl[np][2], bl[np][3]);
                }
            }
        }
    }

    // ---- epilogue: fragment-layout stores (relu handled by next klinear) ----
    float* r0p = ob + (size_t)(p0 + mrow + g) * ND;
    float* r1p = ob + (size_t)(p0 + mrow + g + 8) * ND;
#pragma unroll
    for (int j = 0; j < 16; j++) {
        *(float2*)(r0p + 8 * j + 2 * c) = make_float2(o[j][0], o[j][1]);
        *(float2*)(r1p + 8 * j + 2 * c) = make_float2(o[j][2], o[j][3]);
    }
}

// ============================================================
extern "C" void kernel_launch(void* const* d_in, const int* in_sizes, int n_in,
                              void* d_out, int out_size)
{
    const float* x  = (const float*)d_in[0];
    const float* ew = (const float*)d_in[1];
    const float* W[3]    = {(const float*)d_in[2], (const float*)d_in[4], (const float*)d_in[6]};
    const float* bias[3] = {(const float*)d_in[3], (const float*)d_in[5], (const float*)d_in[7]};
    float* out = (float*)d_out;

    cudaFuncSetAttribute(kaggr_mma, cudaFuncAttributeMaxDynamicSharedMemorySize, SM_TOT);

    dim3 gA(NB * NN / 64);
    dim3 gB(NN / 64, NB);

    for (int layer = 0; layer < 3; layer++) {
        klinear<<<gA, 256>>>(x, W[layer], bias[layer], layer > 0 ? 1 : 0);
        kaggr_mma<<<gB, 128, SM_TOT>>>(ew, out, layer == 2 ? 1 : 0);
    }
}

// round 11
// speedup vs baseline: 1.1792x; 1.1792x over previous
#include <cuda_runtime.h>
#include <cuda_fp16.h>
#include <math.h>

#define NB 8
#define NN 2048
#define ND 128
#define NT 16

// ---------------- scratch (allocation-free device globals) ----------------
__device__ __align__(16) unsigned short g_h1hi[NB * NN * ND];  // fp16 hi of h1 [b,n,d]
__device__ __align__(16) unsigned short g_h1lo[NB * NN * ND];  // fp16 lo (residual)
__device__ __align__(16) float g_rinv[NB * NN];
__device__ __align__(16) float g_agg[NB * NN * ND];            // inter-layer fp32 (pre-relu)

// ---------------- helpers ----------------
__device__ __forceinline__ unsigned smem_u32(const void* p) {
    unsigned a;
    asm("{ .reg .u64 t; cvta.to.shared.u64 t, %1; cvt.u32.u64 %0, t; }" : "=r"(a) : "l"(p));
    return a;
}
__device__ __forceinline__ void ldmx4(unsigned* r, unsigned a) {
    asm volatile("ldmatrix.sync.aligned.m8n8.x4.shared.b16 {%0,%1,%2,%3}, [%4];"
        : "=r"(r[0]), "=r"(r[1]), "=r"(r[2]), "=r"(r[3]) : "r"(a));
}
__device__ __forceinline__ void ldmx4t(unsigned* r, unsigned a) {
    asm volatile("ldmatrix.sync.aligned.m8n8.x4.trans.shared.b16 {%0,%1,%2,%3}, [%4];"
        : "=r"(r[0]), "=r"(r[1]), "=r"(r[2]), "=r"(r[3]) : "r"(a));
}
__device__ __forceinline__ void mma_f16(float* d, const unsigned* a,
                                        unsigned b0, unsigned b1) {
    asm volatile("mma.sync.aligned.m16n8k16.row.col.f32.f16.f16.f32 "
        "{%0,%1,%2,%3},{%4,%5,%6,%7},{%8,%9},{%0,%1,%2,%3};"
        : "+f"(d[0]), "+f"(d[1]), "+f"(d[2]), "+f"(d[3])
        : "r"(a[0]), "r"(a[1]), "r"(a[2]), "r"(a[3]), "r"(b0), "r"(b1));
}
// pack two f32 -> f16x2 (lo half = first arg)
__device__ __forceinline__ unsigned pack_f16(float lo, float hi) {
    unsigned r;
    asm("cvt.rn.f16x2.f32 %0, %1, %2;" : "=r"(r) : "f"(hi), "f"(lo));
    return r;
}
#define CP_ASYNC16(dst, src) \
    asm volatile("cp.async.cg.shared.global [%0], [%1], 16;" \
        :: "r"((unsigned)(dst)), "l"(src) : "memory")
#define CP_COMMIT() asm volatile("cp.async.commit_group;" ::: "memory")
#define CP_WAIT0()  asm volatile("cp.async.wait_group 0;" ::: "memory")

// ============================================================
// klinear: h1 = relu?(hin) @ W + b ; rinv = 1/max(||h1||,eps)
// 32-row tiles (proven fastest shape); emits fp16 hi/lo split.
// ============================================================
__global__ __launch_bounds__(256) void klinear(
    const float* __restrict__ xin, const float* __restrict__ W,
    const float* __restrict__ bias, int use_gagg)
{
    __shared__ float sH[32][128];
    const float* hin = use_gagg ? (const float*)g_agg : xin;
    int tid = threadIdx.x;
    size_t row0 = (size_t)blockIdx.x * 32;

#pragma unroll
    for (int i = tid; i < 32 * 32; i += 256) {
        int r = i >> 5, kb = i & 31;
        float4 v = *(const float4*)(hin + (row0 + r) * (size_t)ND + 4 * kb);
        if (use_gagg) {
            v.x = fmaxf(v.x, 0.0f); v.y = fmaxf(v.y, 0.0f);
            v.z = fmaxf(v.z, 0.0f); v.w = fmaxf(v.w, 0.0f);
        }
        *(float4*)&sH[r][4 * kb] = v;
    }
    __syncthreads();

    int wy = tid >> 5, tx = tid & 31;
    float acc[4][4];
    {
        float4 bv = *(const float4*)(bias + 4 * tx);
#pragma unroll
        for (int i = 0; i < 4; i++) {
            acc[i][0] = bv.x; acc[i][1] = bv.y; acc[i][2] = bv.z; acc[i][3] = bv.w;
        }
    }
#pragma unroll 4
    for (int k = 0; k < ND; k++) {
        float4 wv = *(const float4*)(W + (size_t)k * ND + 4 * tx);
        float hr[4];
#pragma unroll
        for (int i = 0; i < 4; i++) hr[i] = sH[4 * wy + i][k];
#pragma unroll
        for (int i = 0; i < 4; i++) {
            acc[i][0] = fmaf(hr[i], wv.x, acc[i][0]);
            acc[i][1] = fmaf(hr[i], wv.y, acc[i][1]);
            acc[i][2] = fmaf(hr[i], wv.z, acc[i][2]);
            acc[i][3] = fmaf(hr[i], wv.w, acc[i][3]);
        }
    }

#pragma unroll
    for (int i = 0; i < 4; i++) {
        float ss = acc[i][0] * acc[i][0] + acc[i][1] * acc[i][1]
                 + acc[i][2] * acc[i][2] + acc[i][3] * acc[i][3];
#pragma unroll
        for (int o = 16; o > 0; o >>= 1) ss += __shfl_xor_sync(0xffffffffu, ss, o);
        float ri = 1.0f / fmaxf(sqrtf(ss), 1e-12f);
        size_t row = row0 + 4 * wy + i;
        unsigned short ush[4], usl[4];
#pragma unroll
        for (int c2 = 0; c2 < 4; c2++) {
            __half hb = __float2half_rn(acc[i][c2]);
            float res = acc[i][c2] - __half2float(hb);
            ush[c2] = __half_as_ushort(hb);
            usl[c2] = __half_as_ushort(__float2half_rn(res));
        }
        uint2 ph = make_uint2(ush[0] | ((unsigned)ush[1] << 16), ush[2] | ((unsigned)ush[3] << 16));
        uint2 pl = make_uint2(usl[0] | ((unsigned)usl[1] << 16), usl[2] | ((unsigned)usl[3] << 16));
        *(uint2*)(g_h1hi + row * ND + 4 * tx) = ph;
        *(uint2*)(g_h1lo + row * ND + 4 * tx) = pl;
        if (tx == 0) g_rinv[row] = ri;
    }
}

// ============================================================
// kaggr_mma: out[p,:] = sum_q ew[p,q]*rp*rq*(h1_p . h1_q) * h1[q,:]
// fp16 split: GEMM1 3-pass (err ~2^-24), GEMM2 2-pass (S exact x Hq_hi).
// 128-row tiles, 8 warps, cp.async double buffer, 1 CTA/SM.
// ============================================================
#define SROWB 272                 // bytes per smem row (128+8 halfs)
#define TILEB 34816               // one 128-row tile (hi or lo)
#define OFF_HPH 0
#define OFF_HPL TILEB
#define OFF_HQ0 (2 * TILEB)       // buffer 0: hi at +0, lo at +TILEB
#define OFF_HQ1 (4 * TILEB)       // buffer 1
#define OFF_RQ  (6 * TILEB)       // 2 x 512B
#define SM_TOT  (6 * TILEB + 1024)

__global__ __launch_bounds__(256) void kaggr_mma(
    const float* __restrict__ ew, float* __restrict__ dout, int is_last)
{
    extern __shared__ char sm[];
    unsigned sb = smem_u32(sm);
    int tid = threadIdx.x, wid = tid >> 5, lane = tid & 31;
    int b = blockIdx.y, p0 = blockIdx.x * 128;

    const unsigned short* hh = g_h1hi + (size_t)b * NN * ND;
    const unsigned short* hl = g_h1lo + (size_t)b * NN * ND;
    const float* ewb = ew + (size_t)b * NN * NN;
    const float* rb = g_rinv + (size_t)b * NN;
    float* ob = (is_last ? dout : (float*)g_agg) + (size_t)b * NN * ND;

    // persistent Hp hi/lo tile
#pragma unroll
    for (int f = tid; f < 2048; f += 256) {
        int r = f >> 4, ch = f & 15;
        *(uint4*)(sm + OFF_HPH + r * SROWB + ch * 16) =
            *(const uint4*)(hh + (size_t)(p0 + r) * ND + ch * 8);
        *(uint4*)(sm + OFF_HPL + r * SROWB + ch * 16) =
            *(const uint4*)(hl + (size_t)(p0 + r) * ND + ch * 8);
    }

    int g = lane >> 2, c = lane & 3;
    int mrow = wid * 16;
    float rp0 = rb[p0 + mrow + g];
    float rp1 = rb[p0 + mrow + g + 8];
    const float* ew0 = ewb + (size_t)(p0 + mrow + g) * NN;
    const float* ew1 = ewb + (size_t)(p0 + mrow + g + 8) * NN;

    int grp = lane >> 3, wi = lane & 7;
    unsigned offA = (unsigned)((mrow + wi + (grp & 1) * 8) * SROWB + (grp >> 1) * 16);
    unsigned offB = (unsigned)((wi + (grp >> 1) * 8) * SROWB + (grp & 1) * 16);
    unsigned offT = (unsigned)((wi + (grp & 1) * 8) * SROWB + (grp >> 1) * 16);

    float o[16][4];
#pragma unroll
    for (int j = 0; j < 16; j++)
#pragma unroll
        for (int k = 0; k < 4; k++) o[j][k] = 0.0f;

    auto issue_tile = [&](int t, unsigned bufoff) {
        int q0 = t << 7;
#pragma unroll
        for (int f = tid; f < 2048; f += 256) {
            int r = f >> 4, ch = f & 15;
            CP_ASYNC16(sb + bufoff + r * SROWB + ch * 16,
                       hh + (size_t)(q0 + r) * ND + ch * 8);
            CP_ASYNC16(sb + bufoff + TILEB + r * SROWB + ch * 16,
                       hl + (size_t)(q0 + r) * ND + ch * 8);
        }
        if (tid < 32) CP_ASYNC16(sb + OFF_RQ + ((unsigned)(t & 1) << 9) + tid * 16,
                                 rb + q0 + tid * 4);
        CP_COMMIT();
    };

    issue_tile(0, OFF_HQ0);

    for (int t = 0; t < NT; t++) {
        unsigned bufoff = (t & 1) ? OFF_HQ1 : OFF_HQ0;
        CP_WAIT0();
        __syncthreads();
        if (t + 1 < NT) issue_tile(t + 1, (t & 1) ? OFF_HQ0 : OFF_HQ1);

        int q0 = t << 7;
        const float* s_rq = (const float*)(sm + OFF_RQ + ((unsigned)(t & 1) << 9));

#pragma unroll
        for (int nh = 0; nh < 2; nh++) {
            // EW prefetch for this n-half (hidden under GEMM1 MMAs)
            float2 eq0[8], eq1[8];
#pragma unroll
            for (int tl = 0; tl < 8; tl++) {
                int col = q0 + (nh * 8 + tl) * 8 + 2 * c;
                eq0[tl] = *(const float2*)(ew0 + col);
                eq1[tl] = *(const float2*)(ew1 + col);
            }

            // ---- GEMM1: S-half = Hp . Hq^T (fp16 3-pass: hh + lh + hl) ----
            float s[8][4];
#pragma unroll
            for (int j = 0; j < 8; j++)
#pragma unroll
                for (int k = 0; k < 4; k++) s[j][k] = 0.0f;

#pragma unroll
            for (int kk = 0; kk < 8; kk++) {
                unsigned ah[4], al[4];
                ldmx4(ah, sb + OFF_HPH + offA + kk * 32);
                ldmx4(al, sb + OFF_HPL + offA + kk * 32);
                unsigned bh[4][4], bl[4][4];
#pragma unroll
                for (int np = 0; np < 4; np++) {
                    unsigned nb = bufoff + (unsigned)((nh * 4 + np) * 16 * SROWB);
                    ldmx4(bh[np], sb + nb + offB + kk * 32);
                    ldmx4(bl[np], sb + nb + TILEB + offB + kk * 32);
                }
#pragma unroll
                for (int np = 0; np < 4; np++) {   // pass 1: hi*hi
                    mma_f16(s[2 * np], ah, bh[np][0], bh[np][1]);
                    mma_f16(s[2 * np + 1], ah, bh[np][2], bh[np][3]);
                }
#pragma unroll
                for (int np = 0; np < 4; np++) {   // pass 2: lo*hi
                    mma_f16(s[2 * np], al, bh[np][0], bh[np][1]);
                    mma_f16(s[2 * np + 1], al, bh[np][2], bh[np][3]);
                }
#pragma unroll
                for (int np = 0; np < 4; np++) {   // pass 3: hi*lo
                    mma_f16(s[2 * np], ah, bl[np][0], bl[np][1]);
                    mma_f16(s[2 * np + 1], ah, bl[np][2], bl[np][3]);
                }
            }

            // ---- scale + fp16 split -> A fragments (4 kk groups) ----
            unsigned SAh[4][4], SAl[4][4];
#pragma unroll
            for (int tl = 0; tl < 8; tl++) {
                int col = (nh * 8 + tl) * 8 + 2 * c;
                float2 rq2 = *(const float2*)&s_rq[col];
                float2 e0 = eq0[tl];
                float2 e1 = eq1[tl];
                float v0 = s[tl][0] * (rp0 * rq2.x * e0.x);
                float v1 = s[tl][1] * (rp0 * rq2.y * e0.y);
                float v2 = s[tl][2] * (rp1 * rq2.x * e1.x);
                float v3 = s[tl][3] * (rp1 * rq2.y * e1.y);
                __half h0 = __float2half_rn(v0);
                __half h1v = __float2half_rn(v1);
                __half h2 = __float2half_rn(v2);
                __half h3 = __float2half_rn(v3);
                float r0v = v0 - __half2float(h0);
                float r1v = v1 - __half2float(h1v);
                float r2v = v2 - __half2float(h2);
                float r3v = v3 - __half2float(h3);
                int kl = tl >> 1, sl = (tl & 1) * 2;
                SAh[kl][sl]     = (unsigned)__half_as_ushort(h0)
                                | ((unsigned)__half_as_ushort(h1v) << 16);
                SAh[kl][sl + 1] = (unsigned)__half_as_ushort(h2)
                                | ((unsigned)__half_as_ushort(h3) << 16);
                SAl[kl][sl]     = pack_f16(r0v, r1v);
                SAl[kl][sl + 1] = pack_f16(r2v, r3v);
            }

            // ---- GEMM2 (2-pass): o += (Shi + Slo) x Hq_hi ----
#pragma unroll
            for (int kl = 0; kl < 4; kl++) {
                unsigned kb = bufoff + (unsigned)((nh * 4 + kl) * 16 * SROWB);
#pragma unroll
                for (int npg = 0; npg < 2; npg++) {
                    unsigned bh[4][4];
#pragma unroll
                    for (int np = 0; np < 4; np++)
                        ldmx4t(bh[np], sb + kb + offT + (npg * 4 + np) * 32);
#pragma unroll
                    for (int np = 0; np < 4; np++) {   // pass 1: SAh * bh
                        int j = (npg * 4 + np) * 2;
                        mma_f16(o[j], SAh[kl], bh[np][0], bh[np][1]);
                        mma_f16(o[j + 1], SAh[kl], bh[np][2], bh[np][3]);
                    }
#pragma unroll
                    for (int np = 0; np < 4; np++) {   // pass 2: SAl * bh
                        int j = (npg * 4 + np) * 2;
                        mma_f16(o[j], SAl[kl], bh[np][0], bh[np][1]);
                        mma_f16(o[j + 1], SAl[kl], bh[np][2], bh[np][3]);
                    }
                }
            }
        }
    }

    // ---- epilogue: fragment-layout stores (relu handled by next klinear) ----
    float* r0p = ob + (size_t)(p0 + mrow + g) * ND;
    float* r1p = ob + (size_t)(p0 + mrow + g + 8) * ND;
#pragma unroll
    for (int j = 0; j < 16; j++) {
        *(float2*)(r0p + 8 * j + 2 * c) = make_float2(o[j][0], o[j][1]);
        *(float2*)(r1p + 8 * j + 2 * c) = make_float2(o[j][2], o[j][3]);
    }
}

// ============================================================
extern "C" void kernel_launch(void* const* d_in, const int* in_sizes, int n_in,
                              void* d_out, int out_size)
{
    const float* x  = (const float*)d_in[0];
    const float* ew = (const float*)d_in[1];
    const float* W[3]    = {(const float*)d_in[2], (const float*)d_in[4], (const float*)d_in[6]};
    const float* bias[3] = {(const float*)d_in[3], (const float*)d_in[5], (const float*)d_in[7]};
    float* out = (float*)d_out;

    cudaFuncSetAttribute(kaggr_mma, cudaFuncAttributeMaxDynamicSharedMemorySize, SM_TOT);

    dim3 gA(NB * NN / 32);
    dim3 gB(NN / 128, NB);

    for (int layer = 0; layer < 3; layer++) {
        klinear<<<gA, 256>>>(x, W[layer], bias[layer], layer > 0 ? 1 : 0);
        kaggr_mma<<<gB, 256, SM_TOT>>>(ew, out, layer == 2 ? 1 : 0);
    }
}

// round 12
// speedup vs baseline: 1.2721x; 1.0788x over previous
#include <cuda_runtime.h>
#include <cuda_fp16.h>
#include <math.h>

#define NB 8
#define NN 2048
#define ND 128
#define NT 16

// ---------------- scratch (allocation-free device globals) ----------------
__device__ __align__(16) unsigned short g_h1hi[NB * NN * ND];  // fp16 hi of h1 [b,n,d]
__device__ __align__(16) unsigned short g_h1lo[NB * NN * ND];  // fp16 lo (residual)
__device__ __align__(16) float g_rinv[NB * NN];
__device__ __align__(16) float g_agg[NB * NN * ND];            // inter-layer fp32 (pre-relu)

// ---------------- helpers ----------------
__device__ __forceinline__ unsigned smem_u32(const void* p) {
    unsigned a;
    asm("{ .reg .u64 t; cvta.to.shared.u64 t, %1; cvt.u32.u64 %0, t; }" : "=r"(a) : "l"(p));
    return a;
}
__device__ __forceinline__ void ldmx4(unsigned* r, unsigned a) {
    asm volatile("ldmatrix.sync.aligned.m8n8.x4.shared.b16 {%0,%1,%2,%3}, [%4];"
        : "=r"(r[0]), "=r"(r[1]), "=r"(r[2]), "=r"(r[3]) : "r"(a));
}
__device__ __forceinline__ void ldmx4t(unsigned* r, unsigned a) {
    asm volatile("ldmatrix.sync.aligned.m8n8.x4.trans.shared.b16 {%0,%1,%2,%3}, [%4];"
        : "=r"(r[0]), "=r"(r[1]), "=r"(r[2]), "=r"(r[3]) : "r"(a));
}
__device__ __forceinline__ void mma_f16(float* d, const unsigned* a,
                                        unsigned b0, unsigned b1) {
    asm volatile("mma.sync.aligned.m16n8k16.row.col.f32.f16.f16.f32 "
        "{%0,%1,%2,%3},{%4,%5,%6,%7},{%8,%9},{%0,%1,%2,%3};"
        : "+f"(d[0]), "+f"(d[1]), "+f"(d[2]), "+f"(d[3])
        : "r"(a[0]), "r"(a[1]), "r"(a[2]), "r"(a[3]), "r"(b0), "r"(b1));
}
// pack two f32 -> f16x2 (lo half = first arg)
__device__ __forceinline__ unsigned pack_f16(float lo, float hi) {
    unsigned r;
    asm("cvt.rn.f16x2.f32 %0, %1, %2;" : "=r"(r) : "f"(hi), "f"(lo));
    return r;
}
#define CP_ASYNC16(dst, src) \
    asm volatile("cp.async.cg.shared.global [%0], [%1], 16;" \
        :: "r"((unsigned)(dst)), "l"(src) : "memory")
#define CP_COMMIT() asm volatile("cp.async.commit_group;" ::: "memory")
#define CP_WAIT0()  asm volatile("cp.async.wait_group 0;" ::: "memory")

// ============================================================
// klinear: h1 = relu?(hin) @ W + b ; rinv = 1/max(||h1||,eps)
// 32-row tiles; emits fp16 hi/lo split.
// ============================================================
__global__ __launch_bounds__(256) void klinear(
    const float* __restrict__ xin, const float* __restrict__ W,
    const float* __restrict__ bias, int use_gagg)
{
    __shared__ float sH[32][128];
    const float* hin = use_gagg ? (const float*)g_agg : xin;
    int tid = threadIdx.x;
    size_t row0 = (size_t)blockIdx.x * 32;

#pragma unroll
    for (int i = tid; i < 32 * 32; i += 256) {
        int r = i >> 5, kb = i & 31;
        float4 v = *(const float4*)(hin + (row0 + r) * (size_t)ND + 4 * kb);
        if (use_gagg) {
            v.x = fmaxf(v.x, 0.0f); v.y = fmaxf(v.y, 0.0f);
            v.z = fmaxf(v.z, 0.0f); v.w = fmaxf(v.w, 0.0f);
        }
        *(float4*)&sH[r][4 * kb] = v;
    }
    __syncthreads();

    int wy = tid >> 5, tx = tid & 31;
    float acc[4][4];
    {
        float4 bv = *(const float4*)(bias + 4 * tx);
#pragma unroll
        for (int i = 0; i < 4; i++) {
            acc[i][0] = bv.x; acc[i][1] = bv.y; acc[i][2] = bv.z; acc[i][3] = bv.w;
        }
    }
#pragma unroll 4
    for (int k = 0; k < ND; k++) {
        float4 wv = *(const float4*)(W + (size_t)k * ND + 4 * tx);
        float hr[4];
#pragma unroll
        for (int i = 0; i < 4; i++) hr[i] = sH[4 * wy + i][k];
#pragma unroll
        for (int i = 0; i < 4; i++) {
            acc[i][0] = fmaf(hr[i], wv.x, acc[i][0]);
            acc[i][1] = fmaf(hr[i], wv.y, acc[i][1]);
            acc[i][2] = fmaf(hr[i], wv.z, acc[i][2]);
            acc[i][3] = fmaf(hr[i], wv.w, acc[i][3]);
        }
    }

#pragma unroll
    for (int i = 0; i < 4; i++) {
        float ss = acc[i][0] * acc[i][0] + acc[i][1] * acc[i][1]
                 + acc[i][2] * acc[i][2] + acc[i][3] * acc[i][3];
#pragma unroll
        for (int o = 16; o > 0; o >>= 1) ss += __shfl_xor_sync(0xffffffffu, ss, o);
        float ri = 1.0f / fmaxf(sqrtf(ss), 1e-12f);
        size_t row = row0 + 4 * wy + i;
        unsigned short ush[4], usl[4];
#pragma unroll
        for (int c2 = 0; c2 < 4; c2++) {
            __half hb = __float2half_rn(acc[i][c2]);
            float res = acc[i][c2] - __half2float(hb);
            ush[c2] = __half_as_ushort(hb);
            usl[c2] = __half_as_ushort(__float2half_rn(res));
        }
        uint2 ph = make_uint2(ush[0] | ((unsigned)ush[1] << 16), ush[2] | ((unsigned)ush[3] << 16));
        uint2 pl = make_uint2(usl[0] | ((unsigned)usl[1] << 16), usl[2] | ((unsigned)usl[3] << 16));
        *(uint2*)(g_h1hi + row * ND + 4 * tx) = ph;
        *(uint2*)(g_h1lo + row * ND + 4 * tx) = pl;
        if (tx == 0) g_rinv[row] = ri;
    }
}

// ============================================================
// kaggr_mma: out[p,:] = sum_q ew[p,q]*rp*rq*(h1_p . h1_q) * h1[q,:]
// fp16 split, 2-pass both GEMMs:
//   GEMM1: S = (Hp_hi + Hp_lo) . Hq_hi^T   (q-side lo dropped, ~2^-13)
//   GEMM2: o += (S_hi + S_lo) . Hq_hi      (Hq lo dropped, ~2^-13)
// => Hq_lo never loaded: half the cp.async + smem traffic.
// ============================================================
#define SROWB 272                 // bytes per smem row (128+8 halfs)
#define TILEB 34816               // one 128-row tile
#define OFF_HPH 0
#define OFF_HPL TILEB
#define OFF_HQ0 (2 * TILEB)       // buffer 0 (hi only)
#define OFF_HQ1 (3 * TILEB)       // buffer 1 (hi only)
#define OFF_RQ  (4 * TILEB)       // 2 x 512B
#define SM_TOT  (4 * TILEB + 1024)

__global__ __launch_bounds__(256) void kaggr_mma(
    const float* __restrict__ ew, float* __restrict__ dout, int is_last)
{
    extern __shared__ char sm[];
    unsigned sb = smem_u32(sm);
    int tid = threadIdx.x, wid = tid >> 5, lane = tid & 31;
    int b = blockIdx.y, p0 = blockIdx.x * 128;

    const unsigned short* hh = g_h1hi + (size_t)b * NN * ND;
    const unsigned short* hl = g_h1lo + (size_t)b * NN * ND;
    const float* ewb = ew + (size_t)b * NN * NN;
    const float* rb = g_rinv + (size_t)b * NN;
    float* ob = (is_last ? dout : (float*)g_agg) + (size_t)b * NN * ND;

    // persistent Hp hi/lo tile
#pragma unroll
    for (int f = tid; f < 2048; f += 256) {
        int r = f >> 4, ch = f & 15;
        *(uint4*)(sm + OFF_HPH + r * SROWB + ch * 16) =
            *(const uint4*)(hh + (size_t)(p0 + r) * ND + ch * 8);
        *(uint4*)(sm + OFF_HPL + r * SROWB + ch * 16) =
            *(const uint4*)(hl + (size_t)(p0 + r) * ND + ch * 8);
    }

    int g = lane >> 2, c = lane & 3;
    int mrow = wid * 16;
    float rp0 = rb[p0 + mrow + g];
    float rp1 = rb[p0 + mrow + g + 8];
    const float* ew0 = ewb + (size_t)(p0 + mrow + g) * NN;
    const float* ew1 = ewb + (size_t)(p0 + mrow + g + 8) * NN;

    int grp = lane >> 3, wi = lane & 7;
    unsigned offA = (unsigned)((mrow + wi + (grp & 1) * 8) * SROWB + (grp >> 1) * 16);
    unsigned offB = (unsigned)((wi + (grp >> 1) * 8) * SROWB + (grp & 1) * 16);
    unsigned offT = (unsigned)((wi + (grp & 1) * 8) * SROWB + (grp >> 1) * 16);

    float o[16][4];
#pragma unroll
    for (int j = 0; j < 16; j++)
#pragma unroll
        for (int k = 0; k < 4; k++) o[j][k] = 0.0f;

    auto issue_tile = [&](int t, unsigned bufoff) {
        int q0 = t << 7;
#pragma unroll
        for (int f = tid; f < 2048; f += 256) {
            int r = f >> 4, ch = f & 15;
            CP_ASYNC16(sb + bufoff + r * SROWB + ch * 16,
                       hh + (size_t)(q0 + r) * ND + ch * 8);
        }
        if (tid < 32) CP_ASYNC16(sb + OFF_RQ + ((unsigned)(t & 1) << 9) + tid * 16,
                                 rb + q0 + tid * 4);
        CP_COMMIT();
    };

    issue_tile(0, OFF_HQ0);

    for (int t = 0; t < NT; t++) {
        unsigned bufoff = (t & 1) ? OFF_HQ1 : OFF_HQ0;
        CP_WAIT0();
        __syncthreads();
        if (t + 1 < NT) issue_tile(t + 1, (t & 1) ? OFF_HQ0 : OFF_HQ1);

        int q0 = t << 7;
        const float* s_rq = (const float*)(sm + OFF_RQ + ((unsigned)(t & 1) << 9));

#pragma unroll
        for (int nh = 0; nh < 2; nh++) {
            // EW prefetch for this n-half (hidden under GEMM1 MMAs)
            float2 eq0[8], eq1[8];
#pragma unroll
            for (int tl = 0; tl < 8; tl++) {
                int col = q0 + (nh * 8 + tl) * 8 + 2 * c;
                eq0[tl] = *(const float2*)(ew0 + col);
                eq1[tl] = *(const float2*)(ew1 + col);
            }

            // ---- GEMM1: S-half = Hp_full . Hq_hi^T (2-pass: hh + lh) ----
            float s[8][4];
#pragma unroll
            for (int j = 0; j < 8; j++)
#pragma unroll
                for (int k = 0; k < 4; k++) s[j][k] = 0.0f;

#pragma unroll
            for (int kk = 0; kk < 8; kk++) {
                unsigned ah[4], al[4];
                ldmx4(ah, sb + OFF_HPH + offA + kk * 32);
                ldmx4(al, sb + OFF_HPL + offA + kk * 32);
                unsigned bh[4][4];
#pragma unroll
                for (int np = 0; np < 4; np++) {
                    unsigned nb = bufoff + (unsigned)((nh * 4 + np) * 16 * SROWB);
                    ldmx4(bh[np], sb + nb + offB + kk * 32);
                }
#pragma unroll
                for (int np = 0; np < 4; np++) {   // pass 1: hi*hi
                    mma_f16(s[2 * np], ah, bh[np][0], bh[np][1]);
                    mma_f16(s[2 * np + 1], ah, bh[np][2], bh[np][3]);
                }
#pragma unroll
                for (int np = 0; np < 4; np++) {   // pass 2: lo*hi
                    mma_f16(s[2 * np], al, bh[np][0], bh[np][1]);
                    mma_f16(s[2 * np + 1], al, bh[np][2], bh[np][3]);
                }
            }

            // ---- scale + fp16 split -> A fragments (4 kk groups) ----
            unsigned SAh[4][4], SAl[4][4];
#pragma unroll
            for (int tl = 0; tl < 8; tl++) {
                int col = (nh * 8 + tl) * 8 + 2 * c;
                float2 rq2 = *(const float2*)&s_rq[col];
                float2 e0 = eq0[tl];
                float2 e1 = eq1[tl];
                float v0 = s[tl][0] * (rp0 * rq2.x * e0.x);
                float v1 = s[tl][1] * (rp0 * rq2.y * e0.y);
                float v2 = s[tl][2] * (rp1 * rq2.x * e1.x);
                float v3 = s[tl][3] * (rp1 * rq2.y * e1.y);
                __half h0 = __float2half_rn(v0);
                __half h1v = __float2half_rn(v1);
                __half h2 = __float2half_rn(v2);
                __half h3 = __float2half_rn(v3);
                float r0v = v0 - __half2float(h0);
                float r1v = v1 - __half2float(h1v);
                float r2v = v2 - __half2float(h2);
                float r3v = v3 - __half2float(h3);
                int kl = tl >> 1, sl = (tl & 1) * 2;
                SAh[kl][sl]     = (unsigned)__half_as_ushort(h0)
                                | ((unsigned)__half_as_ushort(h1v) << 16);
                SAh[kl][sl + 1] = (unsigned)__half_as_ushort(h2)
                                | ((unsigned)__half_as_ushort(h3) << 16);
                SAl[kl][sl]     = pack_f16(r0v, r1v);
                SAl[kl][sl + 1] = pack_f16(r2v, r3v);
            }

            // ---- GEMM2 (2-pass): o += (Shi + Slo) x Hq_hi ----
#pragma unroll
            for (int kl = 0; kl < 4; kl++) {
                unsigned kb = bufoff + (unsigned)((nh * 4 + kl) * 16 * SROWB);
#pragma unroll
                for (int npg = 0; npg < 2; npg++) {
                    unsigned bh[4][4];
#pragma unroll
                    for (int np = 0; np < 4; np++)
                        ldmx4t(bh[np], sb + kb + offT + (npg * 4 + np) * 32);
#pragma unroll
                    for (int np = 0; np < 4; np++) {   // pass 1: SAh * bh
                        int j = (npg * 4 + np) * 2;
                        mma_f16(o[j], SAh[kl], bh[np][0], bh[np][1]);
                        mma_f16(o[j + 1], SAh[kl], bh[np][2], bh[np][3]);
                    }
#pragma unroll
                    for (int np = 0; np < 4; np++) {   // pass 2: SAl * bh
                        int j = (npg * 4 + np) * 2;
                        mma_f16(o[j], SAl[kl], bh[np][0], bh[np][1]);
                        mma_f16(o[j + 1], SAl[kl], bh[np][2], bh[np][3]);
                    }
                }
            }
        }
    }

    // ---- epilogue: fragment-layout stores (relu handled by next klinear) ----
    float* r0p = ob + (size_t)(p0 + mrow + g) * ND;
    float* r1p = ob + (size_t)(p0 + mrow + g + 8) * ND;
#pragma unroll
    for (int j = 0; j < 16; j++) {
        *(float2*)(r0p + 8 * j + 2 * c) = make_float2(o[j][0], o[j][1]);
        *(float2*)(r1p + 8 * j + 2 * c) = make_float2(o[j][2], o[j][3]);
    }
}

// ============================================================
extern "C" void kernel_launch(void* const* d_in, const int* in_sizes, int n_in,
                              void* d_out, int out_size)
{
    const float* x  = (const float*)d_in[0];
    const float* ew = (const float*)d_in[1];
    const float* W[3]    = {(const float*)d_in[2], (const float*)d_in[4], (const float*)d_in[6]};
    const float* bias[3] = {(const float*)d_in[3], (const float*)d_in[5], (const float*)d_in[7]};
    float* out = (float*)d_out;

    cudaFuncSetAttribute(kaggr_mma, cudaFuncAttributeMaxDynamicSharedMemorySize, SM_TOT);

    dim3 gA(NB * NN / 32);
    dim3 gB(NN / 128, NB);

    for (int layer = 0; layer < 3; layer++) {
        klinear<<<gA, 256>>>(x, W[layer], bias[layer], layer > 0 ? 1 : 0);
        kaggr_mma<<<gB, 256, SM_TOT>>>(ew, out, layer == 2 ? 1 : 0);
    }
}

// round 14
// speedup vs baseline: 1.5316x; 1.2041x over previous
#include <cuda_runtime.h>
#include <cuda_fp16.h>
#include <math.h>

#define NB 8
#define NN 2048
#define ND 128
#define NT 16

// ---------------- scratch (allocation-free device globals) ----------------
__device__ __align__(16) unsigned short g_h1hi[NB * NN * ND];  // fp16 of h1 [b,n,d]
__device__ __align__(16) float g_rinv[NB * NN];
__device__ __align__(16) float g_agg[NB * NN * ND];            // inter-layer fp32 (pre-relu)

// ---------------- helpers ----------------
__device__ __forceinline__ unsigned smem_u32(const void* p) {
    unsigned a;
    asm("{ .reg .u64 t; cvta.to.shared.u64 t, %1; cvt.u32.u64 %0, t; }" : "=r"(a) : "l"(p));
    return a;
}
__device__ __forceinline__ void ldmx4(unsigned* r, unsigned a) {
    asm volatile("ldmatrix.sync.aligned.m8n8.x4.shared.b16 {%0,%1,%2,%3}, [%4];"
        : "=r"(r[0]), "=r"(r[1]), "=r"(r[2]), "=r"(r[3]) : "r"(a));
}
__device__ __forceinline__ void ldmx4t(unsigned* r, unsigned a) {
    asm volatile("ldmatrix.sync.aligned.m8n8.x4.trans.shared.b16 {%0,%1,%2,%3}, [%4];"
        : "=r"(r[0]), "=r"(r[1]), "=r"(r[2]), "=r"(r[3]) : "r"(a));
}
__device__ __forceinline__ void mma_f16(float* d, const unsigned* a,
                                        unsigned b0, unsigned b1) {
    asm volatile("mma.sync.aligned.m16n8k16.row.col.f32.f16.f16.f32 "
        "{%0,%1,%2,%3},{%4,%5,%6,%7},{%8,%9},{%0,%1,%2,%3};"
        : "+f"(d[0]), "+f"(d[1]), "+f"(d[2]), "+f"(d[3])
        : "r"(a[0]), "r"(a[1]), "r"(a[2]), "r"(a[3]), "r"(b0), "r"(b1));
}
// pack two f32 -> f16x2 (lo half = first arg)
__device__ __forceinline__ unsigned pack_f16(float lo, float hi) {
    unsigned r;
    asm("cvt.rn.f16x2.f32 %0, %1, %2;" : "=r"(r) : "f"(hi), "f"(lo));
    return r;
}
#define CP_ASYNC16(dst, src) \
    asm volatile("cp.async.cg.shared.global [%0], [%1], 16;" \
        :: "r"((unsigned)(dst)), "l"(src) : "memory")
#define CP_COMMIT() asm volatile("cp.async.commit_group;" ::: "memory")
#define CP_WAIT0()  asm volatile("cp.async.wait_group 0;" ::: "memory")

// ============================================================
// klinear: h1 = relu?(hin) @ W + b ; rinv = 1/max(||h1||,eps)
// 32-row tiles; emits fp16 h1 (hi only — single-pass MMA downstream).
// ============================================================
__global__ __launch_bounds__(256) void klinear(
    const float* __restrict__ xin, const float* __restrict__ W,
    const float* __restrict__ bias, int use_gagg)
{
    __shared__ float sH[32][128];
    const float* hin = use_gagg ? (const float*)g_agg : xin;
    int tid = threadIdx.x;
    size_t row0 = (size_t)blockIdx.x * 32;

#pragma unroll
    for (int i = tid; i < 32 * 32; i += 256) {
        int r = i >> 5, kb = i & 31;
        float4 v = *(const float4*)(hin + (row0 + r) * (size_t)ND + 4 * kb);
        if (use_gagg) {
            v.x = fmaxf(v.x, 0.0f); v.y = fmaxf(v.y, 0.0f);
            v.z = fmaxf(v.z, 0.0f); v.w = fmaxf(v.w, 0.0f);
        }
        *(float4*)&sH[r][4 * kb] = v;
    }
    __syncthreads();

    int wy = tid >> 5, tx = tid & 31;
    float acc[4][4];
    {
        float4 bv = *(const float4*)(bias + 4 * tx);
#pragma unroll
        for (int i = 0; i < 4; i++) {
            acc[i][0] = bv.x; acc[i][1] = bv.y; acc[i][2] = bv.z; acc[i][3] = bv.w;
        }
    }
#pragma unroll 4
    for (int k = 0; k < ND; k++) {
        float4 wv = *(const float4*)(W + (size_t)k * ND + 4 * tx);
        float hr[4];
#pragma unroll
        for (int i = 0; i < 4; i++) hr[i] = sH[4 * wy + i][k];
#pragma unroll
        for (int i = 0; i < 4; i++) {
            acc[i][0] = fmaf(hr[i], wv.x, acc[i][0]);
            acc[i][1] = fmaf(hr[i], wv.y, acc[i][1]);
            acc[i][2] = fmaf(hr[i], wv.z, acc[i][2]);
            acc[i][3] = fmaf(hr[i], wv.w, acc[i][3]);
        }
    }

#pragma unroll
    for (int i = 0; i < 4; i++) {
        float ss = acc[i][0] * acc[i][0] + acc[i][1] * acc[i][1]
                 + acc[i][2] * acc[i][2] + acc[i][3] * acc[i][3];
#pragma unroll
        for (int o = 16; o > 0; o >>= 1) ss += __shfl_xor_sync(0xffffffffu, ss, o);
        float ri = 1.0f / fmaxf(sqrtf(ss), 1e-12f);
        size_t row = row0 + 4 * wy + i;
        uint2 ph;
        ph.x = pack_f16(acc[i][0], acc[i][1]);
        ph.y = pack_f16(acc[i][2], acc[i][3]);
        *(uint2*)(g_h1hi + row * ND + 4 * tx) = ph;
        if (tx == 0) g_rinv[row] = ri;
    }
}

// ============================================================
// kaggr_mma: out[p,:] = sum_q ew[p,q]*rp*rq*(h1_p . h1_q) * h1[q,:]
// Single-pass fp16 MMA both GEMMs (empirically validated error budget):
//   GEMM1: S = Hp_hi . Hq_hi^T ; GEMM2: o += fp16(S*rp*rq*ew) . Hq_hi
// ============================================================
#define SROWB 272                 // bytes per smem row (128+8 halfs)
#define TILEB 34816               // one 128-row tile
#define OFF_HPH 0
#define OFF_HQ0 TILEB             // buffer 0
#define OFF_HQ1 (2 * TILEB)       // buffer 1
#define OFF_RQ  (3 * TILEB)       // 2 x 512B
#define SM_TOT  (3 * TILEB + 1024)

__global__ __launch_bounds__(256) void kaggr_mma(
    const float* __restrict__ ew, float* __restrict__ dout, int is_last)
{
    extern __shared__ char sm[];
    unsigned sb = smem_u32(sm);
    int tid = threadIdx.x, wid = tid >> 5, lane = tid & 31;
    int b = blockIdx.y, p0 = blockIdx.x * 128;

    const unsigned short* hh = g_h1hi + (size_t)b * NN * ND;
    const float* ewb = ew + (size_t)b * NN * NN;
    const float* rb = g_rinv + (size_t)b * NN;
    float* ob = (is_last ? dout : (float*)g_agg) + (size_t)b * NN * ND;

    // persistent Hp tile
#pragma unroll
    for (int f = tid; f < 2048; f += 256) {
        int r = f >> 4, ch = f & 15;
        *(uint4*)(sm + OFF_HPH + r * SROWB + ch * 16) =
            *(const uint4*)(hh + (size_t)(p0 + r) * ND + ch * 8);
    }

    int g = lane >> 2, c = lane & 3;
    int mrow = wid * 16;
    float rp0 = rb[p0 + mrow + g];
    float rp1 = rb[p0 + mrow + g + 8];
    const float* ew0 = ewb + (size_t)(p0 + mrow + g) * NN;
    const float* ew1 = ewb + (size_t)(p0 + mrow + g + 8) * NN;

    int grp = lane >> 3, wi = lane & 7;
    unsigned offA = (unsigned)((mrow + wi + (grp & 1) * 8) * SROWB + (grp >> 1) * 16);
    unsigned offB = (unsigned)((wi + (grp >> 1) * 8) * SROWB + (grp & 1) * 16);
    unsigned offT = (unsigned)((wi + (grp & 1) * 8) * SROWB + (grp >> 1) * 16);

    float o[16][4];
#pragma unroll
    for (int j = 0; j < 16; j++)
#pragma unroll
        for (int k = 0; k < 4; k++) o[j][k] = 0.0f;

    auto issue_tile = [&](int t, unsigned bufoff) {
        int q0 = t << 7;
#pragma unroll
        for (int f = tid; f < 2048; f += 256) {
            int r = f >> 4, ch = f & 15;
            CP_ASYNC16(sb + bufoff + r * SROWB + ch * 16,
                       hh + (size_t)(q0 + r) * ND + ch * 8);
        }
        if (tid < 32) CP_ASYNC16(sb + OFF_RQ + ((unsigned)(t & 1) << 9) + tid * 16,
                                 rb + q0 + tid * 4);
        CP_COMMIT();
    };

    issue_tile(0, OFF_HQ0);

    for (int t = 0; t < NT; t++) {
        unsigned bufoff = (t & 1) ? OFF_HQ1 : OFF_HQ0;
        CP_WAIT0();
        __syncthreads();
        if (t + 1 < NT) issue_tile(t + 1, (t & 1) ? OFF_HQ0 : OFF_HQ1);

        int q0 = t << 7;
        const float* s_rq = (const float*)(sm + OFF_RQ + ((unsigned)(t & 1) << 9));

#pragma unroll
        for (int nh = 0; nh < 2; nh++) {
            // EW prefetch for this n-half (hidden under GEMM1 MMAs)
            float2 eq0[8], eq1[8];
#pragma unroll
            for (int tl = 0; tl < 8; tl++) {
                int col = q0 + (nh * 8 + tl) * 8 + 2 * c;
                eq0[tl] = *(const float2*)(ew0 + col);
                eq1[tl] = *(const float2*)(ew1 + col);
            }

            // ---- GEMM1: S-half = Hp_hi . Hq_hi^T (single pass) ----
            float s[8][4];
#pragma unroll
            for (int j = 0; j < 8; j++)
#pragma unroll
                for (int k = 0; k < 4; k++) s[j][k] = 0.0f;

#pragma unroll
            for (int kk = 0; kk < 8; kk++) {
                unsigned ah[4];
                ldmx4(ah, sb + OFF_HPH + offA + kk * 32);
                unsigned bh[4][4];
#pragma unroll
                for (int np = 0; np < 4; np++) {
                    unsigned nb = bufoff + (unsigned)((nh * 4 + np) * 16 * SROWB);
                    ldmx4(bh[np], sb + nb + offB + kk * 32);
                }
#pragma unroll
                for (int np = 0; np < 4; np++) {
                    mma_f16(s[2 * np], ah, bh[np][0], bh[np][1]);
                    mma_f16(s[2 * np + 1], ah, bh[np][2], bh[np][3]);
                }
            }

            // ---- scale + pack fp16 -> A fragments (4 kk groups) ----
            unsigned SAh[4][4];
#pragma unroll
            for (int tl = 0; tl < 8; tl++) {
                int col = (nh * 8 + tl) * 8 + 2 * c;
                float2 rq2 = *(const float2*)&s_rq[col];
                float2 e0 = eq0[tl];
                float2 e1 = eq1[tl];
                float v0 = s[tl][0] * (rp0 * rq2.x * e0.x);
                float v1 = s[tl][1] * (rp0 * rq2.y * e0.y);
                float v2 = s[tl][2] * (rp1 * rq2.x * e1.x);
                float v3 = s[tl][3] * (rp1 * rq2.y * e1.y);
                int kl = tl >> 1, sl = (tl & 1) * 2;
                SAh[kl][sl]     = pack_f16(v0, v1);
                SAh[kl][sl + 1] = pack_f16(v2, v3);
            }

            // ---- GEMM2 (single pass): o += S_hi x Hq_hi ----
#pragma unroll
            for (int kl = 0; kl < 4; kl++) {
                unsigned kb = bufoff + (unsigned)((nh * 4 + kl) * 16 * SROWB);
#pragma unroll
                for (int npg = 0; npg < 2; npg++) {
                    unsigned bh[4][4];
#pragma unroll
                    for (int np = 0; np < 4; np++)
                        ldmx4t(bh[np], sb + kb + offT + (npg * 4 + np) * 32);
#pragma unroll
                    for (int np = 0; np < 4; np++) {
                        int j = (npg * 4 + np) * 2;
                        mma_f16(o[j], SAh[kl], bh[np][0], bh[np][1]);
                        mma_f16(o[j + 1], SAh[kl], bh[np][2], bh[np][3]);
                    }
                }
            }
        }
    }

    // ---- epilogue: fragment-layout stores (relu handled by next klinear) ----
    float* r0p = ob + (size_t)(p0 + mrow + g) * ND;
    float* r1p = ob + (size_t)(p0 + mrow + g + 8) * ND;
#pragma unroll
    for (int j = 0; j < 16; j++) {
        *(float2*)(r0p + 8 * j + 2 * c) = make_float2(o[j][0], o[j][1]);
        *(float2*)(r1p + 8 * j + 2 * c) = make_float2(o[j][2], o[j][3]);
    }
}

// ============================================================
extern "C" void kernel_launch(void* const* d_in, const int* in_sizes, int n_in,
                              void* d_out, int out_size)
{
    const float* x  = (const float*)d_in[0];
    const float* ew = (const float*)d_in[1];
    const float* W[3]    = {(const float*)d_in[2], (const float*)d_in[4], (const float*)d_in[6]};
    const float* bias[3] = {(const float*)d_in[3], (const float*)d_in[5], (const float*)d_in[7]};
    float* out = (float*)d_out;

    cudaFuncSetAttribute(kaggr_mma, cudaFuncAttributeMaxDynamicSharedMemorySize, SM_TOT);

    dim3 gA(NB * NN / 32);
    dim3 gB(NN / 128, NB);

    for (int layer = 0; layer < 3; layer++) {
        klinear<<<gA, 256>>>(x, W[layer], bias[layer], layer > 0 ? 1 : 0);
        kaggr_mma<<<gB, 256, SM_TOT>>>(ew, out, layer == 2 ? 1 : 0);
    }
}

// round 15
// speedup vs baseline: 1.8650x; 1.2176x over previous
#include <cuda_runtime.h>
#include <cuda_fp16.h>
#include <math.h>

#define NB 8
#define NN 2048
#define ND 128
#define NT 16

// ---------------- scratch (allocation-free device globals) ----------------
__device__ __align__(16) unsigned short g_h1hi[NB * NN * ND];  // fp16 of h1 [b,n,d]
__device__ __align__(16) float g_rinv[NB * NN];
__device__ __align__(16) float g_agg[NB * NN * ND];            // inter-layer fp32 (pre-relu)

// ---------------- helpers ----------------
__device__ __forceinline__ unsigned smem_u32(const void* p) {
    unsigned a;
    asm("{ .reg .u64 t; cvta.to.shared.u64 t, %1; cvt.u32.u64 %0, t; }" : "=r"(a) : "l"(p));
    return a;
}
__device__ __forceinline__ void ldmx4(unsigned* r, unsigned a) {
    asm volatile("ldmatrix.sync.aligned.m8n8.x4.shared.b16 {%0,%1,%2,%3}, [%4];"
        : "=r"(r[0]), "=r"(r[1]), "=r"(r[2]), "=r"(r[3]) : "r"(a));
}
__device__ __forceinline__ void ldmx4t(unsigned* r, unsigned a) {
    asm volatile("ldmatrix.sync.aligned.m8n8.x4.trans.shared.b16 {%0,%1,%2,%3}, [%4];"
        : "=r"(r[0]), "=r"(r[1]), "=r"(r[2]), "=r"(r[3]) : "r"(a));
}
__device__ __forceinline__ void mma_f16(float* d, const unsigned* a,
                                        unsigned b0, unsigned b1) {
    asm volatile("mma.sync.aligned.m16n8k16.row.col.f32.f16.f16.f32 "
        "{%0,%1,%2,%3},{%4,%5,%6,%7},{%8,%9},{%0,%1,%2,%3};"
        : "+f"(d[0]), "+f"(d[1]), "+f"(d[2]), "+f"(d[3])
        : "r"(a[0]), "r"(a[1]), "r"(a[2]), "r"(a[3]), "r"(b0), "r"(b1));
}
// pack two f32 -> f16x2 (lo half = first arg)
__device__ __forceinline__ unsigned pack_f16(float lo, float hi) {
    unsigned r;
    asm("cvt.rn.f16x2.f32 %0, %1, %2;" : "=r"(r) : "f"(hi), "f"(lo));
    return r;
}
#define CP_ASYNC16(dst, src) \
    asm volatile("cp.async.cg.shared.global [%0], [%1], 16;" \
        :: "r"((unsigned)(dst)), "l"(src) : "memory")
#define CP_COMMIT() asm volatile("cp.async.commit_group;" ::: "memory")
#define CP_WAIT0()  asm volatile("cp.async.wait_group 0;" ::: "memory")

#define SROWB 272                 // bytes per smem row (128+8 halfs)
#define TILEB 34816               // one 128-row tile

// ============================================================
// klinear_mma: h1 = relu?(hin) @ W + b ; rinv = 1/||h1||
// Tensor-core version: fp16 3-pass split (hh+lh+hl, err ~2^-22).
// 128-row tiles, 8 warps; emits fp16 h1 + fp32 rinv.
// ============================================================
#define KL_XH 0
#define KL_XL TILEB
#define KL_WH (2 * TILEB)
#define KL_WL (3 * TILEB)
#define KL_SMEM (4 * TILEB)

__global__ __launch_bounds__(256) void klinear_mma(
    const float* __restrict__ xin, const float* __restrict__ W,
    const float* __restrict__ bias, int use_gagg)
{
    extern __shared__ char sm[];
    unsigned sb = smem_u32(sm);
    int tid = threadIdx.x, wid = tid >> 5, lane = tid & 31;
    const float* hin = use_gagg ? (const float*)g_agg : xin;
    size_t row0 = (size_t)blockIdx.x * 128;

    // convert x tile (+relu) and W to fp16 hi/lo in padded smem
#pragma unroll
    for (int f = tid; f < 2048; f += 256) {
        int r = f >> 4, ch = f & 15;
        // x rows
        {
            const float* src = hin + (row0 + r) * (size_t)ND + ch * 8;
            float4 a = *(const float4*)(src);
            float4 bq = *(const float4*)(src + 4);
            if (use_gagg) {
                a.x = fmaxf(a.x, 0.f); a.y = fmaxf(a.y, 0.f);
                a.z = fmaxf(a.z, 0.f); a.w = fmaxf(a.w, 0.f);
                bq.x = fmaxf(bq.x, 0.f); bq.y = fmaxf(bq.y, 0.f);
                bq.z = fmaxf(bq.z, 0.f); bq.w = fmaxf(bq.w, 0.f);
            }
            float v[8] = {a.x, a.y, a.z, a.w, bq.x, bq.y, bq.z, bq.w};
            unsigned hi[4], lo[4];
#pragma unroll
            for (int u = 0; u < 4; u++) {
                __half h0 = __float2half_rn(v[2 * u]);
                __half h1 = __float2half_rn(v[2 * u + 1]);
                hi[u] = (unsigned)__half_as_ushort(h0)
                      | ((unsigned)__half_as_ushort(h1) << 16);
                lo[u] = pack_f16(v[2 * u] - __half2float(h0),
                                 v[2 * u + 1] - __half2float(h1));
            }
            *(uint4*)(sm + KL_XH + r * SROWB + ch * 16) = *(uint4*)hi;
            *(uint4*)(sm + KL_XL + r * SROWB + ch * 16) = *(uint4*)lo;
        }
        // W rows [k][n]
        {
            const float* src = W + (size_t)r * ND + ch * 8;
            float4 a = *(const float4*)(src);
            float4 bq = *(const float4*)(src + 4);
            float v[8] = {a.x, a.y, a.z, a.w, bq.x, bq.y, bq.z, bq.w};
            unsigned hi[4], lo[4];
#pragma unroll
            for (int u = 0; u < 4; u++) {
                __half h0 = __float2half_rn(v[2 * u]);
                __half h1 = __float2half_rn(v[2 * u + 1]);
                hi[u] = (unsigned)__half_as_ushort(h0)
                      | ((unsigned)__half_as_ushort(h1) << 16);
                lo[u] = pack_f16(v[2 * u] - __half2float(h0),
                                 v[2 * u + 1] - __half2float(h1));
            }
            *(uint4*)(sm + KL_WH + r * SROWB + ch * 16) = *(uint4*)hi;
            *(uint4*)(sm + KL_WL + r * SROWB + ch * 16) = *(uint4*)lo;
        }
    }
    __syncthreads();

    int g = lane >> 2, c = lane & 3;
    int mrow = wid * 16;
    int grp = lane >> 3, wi = lane & 7;
    unsigned offA = (unsigned)((mrow + wi + (grp & 1) * 8) * SROWB + (grp >> 1) * 16);
    unsigned offT = (unsigned)((wi + (grp & 1) * 8) * SROWB + (grp >> 1) * 16);

    float o[16][4];
#pragma unroll
    for (int j = 0; j < 16; j++)
#pragma unroll
        for (int k = 0; k < 4; k++) o[j][k] = 0.0f;

    // h1 = x @ W : 8 k-chunks of 16, B via ldmx4t on [k][n] W
#pragma unroll
    for (int kl = 0; kl < 8; kl++) {
        unsigned ah[4], al[4];
        ldmx4(ah, sb + KL_XH + offA + kl * 32);
        ldmx4(al, sb + KL_XL + offA + kl * 32);
        unsigned kb = (unsigned)(kl * 16 * SROWB);
#pragma unroll
        for (int npg = 0; npg < 2; npg++) {
            unsigned bh[4][4], bl[4][4];
#pragma unroll
            for (int np = 0; np < 4; np++) {
                ldmx4t(bh[np], sb + KL_WH + offT + kb + (npg * 4 + np) * 32);
                ldmx4t(bl[np], sb + KL_WL + offT + kb + (npg * 4 + np) * 32);
            }
#pragma unroll
            for (int np = 0; np < 4; np++) {   // pass 1: xh * Wh
                int j = (npg * 4 + np) * 2;
                mma_f16(o[j], ah, bh[np][0], bh[np][1]);
                mma_f16(o[j + 1], ah, bh[np][2], bh[np][3]);
            }
#pragma unroll
            for (int np = 0; np < 4; np++) {   // pass 2: xl * Wh
                int j = (npg * 4 + np) * 2;
                mma_f16(o[j], al, bh[np][0], bh[np][1]);
                mma_f16(o[j + 1], al, bh[np][2], bh[np][3]);
            }
#pragma unroll
            for (int np = 0; np < 4; np++) {   // pass 3: xh * Wl
                int j = (npg * 4 + np) * 2;
                mma_f16(o[j], ah, bl[np][0], bl[np][1]);
                mma_f16(o[j + 1], ah, bl[np][2], bl[np][3]);
            }
        }
    }

    // bias add + row norms (fragment layout: rows mrow+g and mrow+g+8)
    float ss0 = 0.0f, ss1 = 0.0f;
#pragma unroll
    for (int j = 0; j < 16; j++) {
        float2 bv = *(const float2*)(bias + 8 * j + 2 * c);
        o[j][0] += bv.x; o[j][1] += bv.y;
        o[j][2] += bv.x; o[j][3] += bv.y;
        ss0 += o[j][0] * o[j][0] + o[j][1] * o[j][1];
        ss1 += o[j][2] * o[j][2] + o[j][3] * o[j][3];
    }
    // reduce over the 4 lanes (c) of each row group (quad shuffle)
#pragma unroll
    for (int off = 1; off < 4; off <<= 1) {
        ss0 += __shfl_xor_sync(0xffffffffu, ss0, off);
        ss1 += __shfl_xor_sync(0xffffffffu, ss1, off);
    }
    size_t row0g = row0 + mrow + g;
    if (c == 0) {
        g_rinv[row0g]     = 1.0f / fmaxf(sqrtf(ss0), 1e-12f);
        g_rinv[row0g + 8] = 1.0f / fmaxf(sqrtf(ss1), 1e-12f);
    }

    // store h1 as fp16 (half2 per fragment pair)
    unsigned short* d0 = g_h1hi + row0g * ND;
    unsigned short* d1 = g_h1hi + (row0g + 8) * ND;
#pragma unroll
    for (int j = 0; j < 16; j++) {
        *(unsigned*)(d0 + 8 * j + 2 * c) = pack_f16(o[j][0], o[j][1]);
        *(unsigned*)(d1 + 8 * j + 2 * c) = pack_f16(o[j][2], o[j][3]);
    }
}

// ============================================================
// kaggr_mma: out[p,:] = sum_q ew[p,q]*rp*rq*(h1_p . h1_q) * h1[q,:]
// Single-pass fp16 MMA both GEMMs (unchanged from R13 passing version).
// ============================================================
#define OFF_HPH 0
#define OFF_HQ0 TILEB             // buffer 0
#define OFF_HQ1 (2 * TILEB)       // buffer 1
#define OFF_RQ  (3 * TILEB)       // 2 x 512B
#define SM_TOT  (3 * TILEB + 1024)

__global__ __launch_bounds__(256) void kaggr_mma(
    const float* __restrict__ ew, float* __restrict__ dout, int is_last)
{
    extern __shared__ char sm[];
    unsigned sb = smem_u32(sm);
    int tid = threadIdx.x, wid = tid >> 5, lane = tid & 31;
    int b = blockIdx.y, p0 = blockIdx.x * 128;

    const unsigned short* hh = g_h1hi + (size_t)b * NN * ND;
    const float* ewb = ew + (size_t)b * NN * NN;
    const float* rb = g_rinv + (size_t)b * NN;
    float* ob = (is_last ? dout : (float*)g_agg) + (size_t)b * NN * ND;

    // persistent Hp tile
#pragma unroll
    for (int f = tid; f < 2048; f += 256) {
        int r = f >> 4, ch = f & 15;
        *(uint4*)(sm + OFF_HPH + r * SROWB + ch * 16) =
            *(const uint4*)(hh + (size_t)(p0 + r) * ND + ch * 8);
    }

    int g = lane >> 2, c = lane & 3;
    int mrow = wid * 16;
    float rp0 = rb[p0 + mrow + g];
    float rp1 = rb[p0 + mrow + g + 8];
    const float* ew0 = ewb + (size_t)(p0 + mrow + g) * NN;
    const float* ew1 = ewb + (size_t)(p0 + mrow + g + 8) * NN;

    int grp = lane >> 3, wi = lane & 7;
    unsigned offA = (unsigned)((mrow + wi + (grp & 1) * 8) * SROWB + (grp >> 1) * 16);
    unsigned offB = (unsigned)((wi + (grp >> 1) * 8) * SROWB + (grp & 1) * 16);
    unsigned offT = (unsigned)((wi + (grp & 1) * 8) * SROWB + (grp >> 1) * 16);

    float o[16][4];
#pragma unroll
    for (int j = 0; j < 16; j++)
#pragma unroll
        for (int k = 0; k < 4; k++) o[j][k] = 0.0f;

    auto issue_tile = [&](int t, unsigned bufoff) {
        int q0 = t << 7;
#pragma unroll
        for (int f = tid; f < 2048; f += 256) {
            int r = f >> 4, ch = f & 15;
            CP_ASYNC16(sb + bufoff + r * SROWB + ch * 16,
                       hh + (size_t)(q0 + r) * ND + ch * 8);
        }
        if (tid < 32) CP_ASYNC16(sb + OFF_RQ + ((unsigned)(t & 1) << 9) + tid * 16,
                                 rb + q0 + tid * 4);
        CP_COMMIT();
    };

    issue_tile(0, OFF_HQ0);

    for (int t = 0; t < NT; t++) {
        unsigned bufoff = (t & 1) ? OFF_HQ1 : OFF_HQ0;
        CP_WAIT0();
        __syncthreads();
        if (t + 1 < NT) issue_tile(t + 1, (t & 1) ? OFF_HQ0 : OFF_HQ1);

        int q0 = t << 7;
        const float* s_rq = (const float*)(sm + OFF_RQ + ((unsigned)(t & 1) << 9));

#pragma unroll
        for (int nh = 0; nh < 2; nh++) {
            // EW prefetch for this n-half (hidden under GEMM1 MMAs)
            float2 eq0[8], eq1[8];
#pragma unroll
            for (int tl = 0; tl < 8; tl++) {
                int col = q0 + (nh * 8 + tl) * 8 + 2 * c;
                eq0[tl] = *(const float2*)(ew0 + col);
                eq1[tl] = *(const float2*)(ew1 + col);
            }

            // ---- GEMM1: S-half = Hp_hi . Hq_hi^T (single pass) ----
            float s[8][4];
#pragma unroll
            for (int j = 0; j < 8; j++)
#pragma unroll
                for (int k = 0; k < 4; k++) s[j][k] = 0.0f;

#pragma unroll
            for (int kk = 0; kk < 8; kk++) {
                unsigned ah[4];
                ldmx4(ah, sb + OFF_HPH + offA + kk * 32);
                unsigned bh[4][4];
#pragma unroll
                for (int np = 0; np < 4; np++) {
                    unsigned nb = bufoff + (unsigned)((nh * 4 + np) * 16 * SROWB);
                    ldmx4(bh[np], sb + nb + offB + kk * 32);
                }
#pragma unroll
                for (int np = 0; np < 4; np++) {
                    mma_f16(s[2 * np], ah, bh[np][0], bh[np][1]);
                    mma_f16(s[2 * np + 1], ah, bh[np][2], bh[np][3]);
                }
            }

            // ---- scale + pack fp16 -> A fragments (4 kk groups) ----
            unsigned SAh[4][4];
#pragma unroll
            for (int tl = 0; tl < 8; tl++) {
                int col = (nh * 8 + tl) * 8 + 2 * c;
                float2 rq2 = *(const float2*)&s_rq[col];
                float2 e0 = eq0[tl];
                float2 e1 = eq1[tl];
                float v0 = s[tl][0] * (rp0 * rq2.x * e0.x);
                float v1 = s[tl][1] * (rp0 * rq2.y * e0.y);
                float v2 = s[tl][2] * (rp1 * rq2.x * e1.x);
                float v3 = s[tl][3] * (rp1 * rq2.y * e1.y);
                int kl = tl >> 1, sl = (tl & 1) * 2;
                SAh[kl][sl]     = pack_f16(v0, v1);
                SAh[kl][sl + 1] = pack_f16(v2, v3);
            }

            // ---- GEMM2 (single pass): o += S_hi x Hq_hi ----
#pragma unroll
            for (int kl = 0; kl < 4; kl++) {
                unsigned kb = bufoff + (unsigned)((nh * 4 + kl) * 16 * SROWB);
#pragma unroll
                for (int npg = 0; npg < 2; npg++) {
                    unsigned bh[4][4];
#pragma unroll
                    for (int np = 0; np < 4; np++)
                        ldmx4t(bh[np], sb + kb + offT + (npg * 4 + np) * 32);
#pragma unroll
                    for (int np = 0; np < 4; np++) {
                        int j = (npg * 4 + np) * 2;
                        mma_f16(o[j], SAh[kl], bh[np][0], bh[np][1]);
                        mma_f16(o[j + 1], SAh[kl], bh[np][2], bh[np][3]);
                    }
                }
            }
        }
    }

    // ---- epilogue: fragment-layout stores (relu handled by next klinear) ----
    float* r0p = ob + (size_t)(p0 + mrow + g) * ND;
    float* r1p = ob + (size_t)(p0 + mrow + g + 8) * ND;
#pragma unroll
    for (int j = 0; j < 16; j++) {
        *(float2*)(r0p + 8 * j + 2 * c) = make_float2(o[j][0], o[j][1]);
        *(float2*)(r1p + 8 * j + 2 * c) = make_float2(o[j][2], o[j][3]);
    }
}

// ============================================================
extern "C" void kernel_launch(void* const* d_in, const int* in_sizes, int n_in,
                              void* d_out, int out_size)
{
    const float* x  = (const float*)d_in[0];
    const float* ew = (const float*)d_in[1];
    const float* W[3]    = {(const float*)d_in[2], (const float*)d_in[4], (const float*)d_in[6]};
    const float* bias[3] = {(const float*)d_in[3], (const float*)d_in[5], (const float*)d_in[7]};
    float* out = (float*)d_out;

    cudaFuncSetAttribute(klinear_mma, cudaFuncAttributeMaxDynamicSharedMemorySize, KL_SMEM);
    cudaFuncSetAttribute(kaggr_mma, cudaFuncAttributeMaxDynamicSharedMemorySize, SM_TOT);

    dim3 gA(NB * NN / 128);
    dim3 gB(NN / 128, NB);

    for (int layer = 0; layer < 3; layer++) {
        klinear_mma<<<gA, 256, KL_SMEM>>>(x, W[layer], bias[layer], layer > 0 ? 1 : 0);
        kaggr_mma<<<gB, 256, SM_TOT>>>(ew, out, layer == 2 ? 1 : 0);
    }
}

// round 16
// speedup vs baseline: 2.2045x; 1.1820x over previous
#include <cuda_runtime.h>
#include <cuda_fp16.h>
#include <math.h>

#define NB 8
#define NN 2048
#define ND 128
#define NT 16

// ---------------- scratch (allocation-free device globals) ----------------
__device__ __align__(16) unsigned short g_h1hi[NB * NN * ND];  // fp16 of h1 [b,n,d]
__device__ __align__(16) float g_rinv[NB * NN];

// ---------------- helpers ----------------
__device__ __forceinline__ unsigned smem_u32(const void* p) {
    unsigned a;
    asm("{ .reg .u64 t; cvta.to.shared.u64 t, %1; cvt.u32.u64 %0, t; }" : "=r"(a) : "l"(p));
    return a;
}
__device__ __forceinline__ void ldmx4(unsigned* r, unsigned a) {
    asm volatile("ldmatrix.sync.aligned.m8n8.x4.shared.b16 {%0,%1,%2,%3}, [%4];"
        : "=r"(r[0]), "=r"(r[1]), "=r"(r[2]), "=r"(r[3]) : "r"(a));
}
__device__ __forceinline__ void ldmx4t(unsigned* r, unsigned a) {
    asm volatile("ldmatrix.sync.aligned.m8n8.x4.trans.shared.b16 {%0,%1,%2,%3}, [%4];"
        : "=r"(r[0]), "=r"(r[1]), "=r"(r[2]), "=r"(r[3]) : "r"(a));
}
__device__ __forceinline__ void mma_f16(float* d, const unsigned* a,
                                        unsigned b0, unsigned b1) {
    asm volatile("mma.sync.aligned.m16n8k16.row.col.f32.f16.f16.f32 "
        "{%0,%1,%2,%3},{%4,%5,%6,%7},{%8,%9},{%0,%1,%2,%3};"
        : "+f"(d[0]), "+f"(d[1]), "+f"(d[2]), "+f"(d[3])
        : "r"(a[0]), "r"(a[1]), "r"(a[2]), "r"(a[3]), "r"(b0), "r"(b1));
}
// pack two f32 -> f16x2 (lo half = first arg)
__device__ __forceinline__ unsigned pack_f16(float lo, float hi) {
    unsigned r;
    asm("cvt.rn.f16x2.f32 %0, %1, %2;" : "=r"(r) : "f"(hi), "f"(lo));
    return r;
}
#define CP_ASYNC16(dst, src) \
    asm volatile("cp.async.cg.shared.global [%0], [%1], 16;" \
        :: "r"((unsigned)(dst)), "l"(src) : "memory")
#define CP_COMMIT() asm volatile("cp.async.commit_group;" ::: "memory")
#define CP_WAIT0()  asm volatile("cp.async.wait_group 0;" ::: "memory")

#define SROWB 272                 // bytes per smem row (128+8 halfs)
#define TILEB 34816               // one 128-row tile

// ---- fp16 hi/lo split of 8 floats -> two uint4 ----
__device__ __forceinline__ void split8(const float* v, uint4* hi4, uint4* lo4) {
    unsigned hi[4], lo[4];
#pragma unroll
    for (int u = 0; u < 4; u++) {
        __half h0 = __float2half_rn(v[2 * u]);
        __half h1 = __float2half_rn(v[2 * u + 1]);
        hi[u] = (unsigned)__half_as_ushort(h0) | ((unsigned)__half_as_ushort(h1) << 16);
        lo[u] = pack_f16(v[2 * u] - __half2float(h0), v[2 * u + 1] - __half2float(h1));
    }
    *hi4 = *(uint4*)hi;
    *lo4 = *(uint4*)lo;
}

// ============================================================
// klinear_mma: h1 = x @ W + b ; rinv = 1/||h1||   (layer 0 only)
// fp16 3-pass split; 128-row tiles, 8 warps.
// ============================================================
#define KL_XH 0
#define KL_XL TILEB
#define KL_WH (2 * TILEB)
#define KL_WL (3 * TILEB)
#define KL_SMEM (4 * TILEB)

__global__ __launch_bounds__(256) void klinear_mma(
    const float* __restrict__ xin, const float* __restrict__ W,
    const float* __restrict__ bias)
{
    extern __shared__ char sm[];
    unsigned sb = smem_u32(sm);
    int tid = threadIdx.x, wid = tid >> 5, lane = tid & 31;
    size_t row0 = (size_t)blockIdx.x * 128;

#pragma unroll
    for (int f = tid; f < 2048; f += 256) {
        int r = f >> 4, ch = f & 15;
        {
            const float* src = xin + (row0 + r) * (size_t)ND + ch * 8;
            float v[8];
#pragma unroll
            for (int u = 0; u < 8; u++) v[u] = src[u];
            split8(v, (uint4*)(sm + KL_XH + r * SROWB + ch * 16),
                      (uint4*)(sm + KL_XL + r * SROWB + ch * 16));
        }
        {
            const float* src = W + (size_t)r * ND + ch * 8;
            float v[8];
#pragma unroll
            for (int u = 0; u < 8; u++) v[u] = src[u];
            split8(v, (uint4*)(sm + KL_WH + r * SROWB + ch * 16),
                      (uint4*)(sm + KL_WL + r * SROWB + ch * 16));
        }
    }
    __syncthreads();

    int g = lane >> 2, c = lane & 3;
    int mrow = wid * 16;
    int grp = lane >> 3, wi = lane & 7;
    unsigned offA = (unsigned)((mrow + wi + (grp & 1) * 8) * SROWB + (grp >> 1) * 16);
    unsigned offT = (unsigned)((wi + (grp & 1) * 8) * SROWB + (grp >> 1) * 16);

    float o[16][4];
#pragma unroll
    for (int j = 0; j < 16; j++)
#pragma unroll
        for (int k = 0; k < 4; k++) o[j][k] = 0.0f;

#pragma unroll
    for (int kl = 0; kl < 8; kl++) {
        unsigned ah[4], al[4];
        ldmx4(ah, sb + KL_XH + offA + kl * 32);
        ldmx4(al, sb + KL_XL + offA + kl * 32);
        unsigned kb = (unsigned)(kl * 16 * SROWB);
#pragma unroll
        for (int npg = 0; npg < 2; npg++) {
            unsigned bh[4][4], bl[4][4];
#pragma unroll
            for (int np = 0; np < 4; np++) {
                ldmx4t(bh[np], sb + KL_WH + offT + kb + (npg * 4 + np) * 32);
                ldmx4t(bl[np], sb + KL_WL + offT + kb + (npg * 4 + np) * 32);
            }
#pragma unroll
            for (int np = 0; np < 4; np++) {
                int j = (npg * 4 + np) * 2;
                mma_f16(o[j], ah, bh[np][0], bh[np][1]);
                mma_f16(o[j + 1], ah, bh[np][2], bh[np][3]);
            }
#pragma unroll
            for (int np = 0; np < 4; np++) {
                int j = (npg * 4 + np) * 2;
                mma_f16(o[j], al, bh[np][0], bh[np][1]);
                mma_f16(o[j + 1], al, bh[np][2], bh[np][3]);
            }
#pragma unroll
            for (int np = 0; np < 4; np++) {
                int j = (npg * 4 + np) * 2;
                mma_f16(o[j], ah, bl[np][0], bl[np][1]);
                mma_f16(o[j + 1], ah, bl[np][2], bl[np][3]);
            }
        }
    }

    float ss0 = 0.0f, ss1 = 0.0f;
#pragma unroll
    for (int j = 0; j < 16; j++) {
        float2 bv = *(const float2*)(bias + 8 * j + 2 * c);
        o[j][0] += bv.x; o[j][1] += bv.y;
        o[j][2] += bv.x; o[j][3] += bv.y;
        ss0 += o[j][0] * o[j][0] + o[j][1] * o[j][1];
        ss1 += o[j][2] * o[j][2] + o[j][3] * o[j][3];
    }
#pragma unroll
    for (int off = 1; off < 4; off <<= 1) {
        ss0 += __shfl_xor_sync(0xffffffffu, ss0, off);
        ss1 += __shfl_xor_sync(0xffffffffu, ss1, off);
    }
    size_t row0g = row0 + mrow + g;
    if (c == 0) {
        g_rinv[row0g]     = 1.0f / fmaxf(sqrtf(ss0), 1e-12f);
        g_rinv[row0g + 8] = 1.0f / fmaxf(sqrtf(ss1), 1e-12f);
    }
    unsigned short* d0 = g_h1hi + row0g * ND;
    unsigned short* d1 = g_h1hi + (row0g + 8) * ND;
#pragma unroll
    for (int j = 0; j < 16; j++) {
        *(unsigned*)(d0 + 8 * j + 2 * c) = pack_f16(o[j][0], o[j][1]);
        *(unsigned*)(d1 + 8 * j + 2 * c) = pack_f16(o[j][2], o[j][3]);
    }
}

// ============================================================
// kaggr_fused: aggregation (single-pass fp16 MMA) + fused next-layer
// linear (3-pass) in epilogue. Last layer stores fp32 to dout.
// ============================================================
#define OFF_HPH 0
#define OFF_HQ0 TILEB             // q-tile buffer 0 / epilogue x_hi
#define OFF_HQ1 (2 * TILEB)       // q-tile buffer 1 / epilogue x_lo
#define OFF_WH  (3 * TILEB)
#define OFF_WL  (4 * TILEB)
#define OFF_RQ  (5 * TILEB)       // 2 x 512B
#define SM_TOT  (5 * TILEB + 1024)

__global__ __launch_bounds__(256) void kaggr_fused(
    const float* __restrict__ ew, const float* __restrict__ Wn,
    const float* __restrict__ bn, float* __restrict__ dout, int is_last)
{
    extern __shared__ char sm[];
    unsigned sb = smem_u32(sm);
    int tid = threadIdx.x, wid = tid >> 5, lane = tid & 31;
    int b = blockIdx.y, p0 = blockIdx.x * 128;

    const unsigned short* hh = g_h1hi + (size_t)b * NN * ND;
    const float* ewb = ew + (size_t)b * NN * NN;
    const float* rb = g_rinv + (size_t)b * NN;

    // persistent Hp tile (+ W conversion for the fused linear)
#pragma unroll
    for (int f = tid; f < 2048; f += 256) {
        int r = f >> 4, ch = f & 15;
        *(uint4*)(sm + OFF_HPH + r * SROWB + ch * 16) =
            *(const uint4*)(hh + (size_t)(p0 + r) * ND + ch * 8);
        if (!is_last) {
            const float* src = Wn + (size_t)r * ND + ch * 8;
            float v[8];
#pragma unroll
            for (int u = 0; u < 8; u++) v[u] = src[u];
            split8(v, (uint4*)(sm + OFF_WH + r * SROWB + ch * 16),
                      (uint4*)(sm + OFF_WL + r * SROWB + ch * 16));
        }
    }

    int g = lane >> 2, c = lane & 3;
    int mrow = wid * 16;
    float rp0 = rb[p0 + mrow + g];
    float rp1 = rb[p0 + mrow + g + 8];
    const float* ew0 = ewb + (size_t)(p0 + mrow + g) * NN;
    const float* ew1 = ewb + (size_t)(p0 + mrow + g + 8) * NN;

    int grp = lane >> 3, wi = lane & 7;
    unsigned offA = (unsigned)((mrow + wi + (grp & 1) * 8) * SROWB + (grp >> 1) * 16);
    unsigned offB = (unsigned)((wi + (grp >> 1) * 8) * SROWB + (grp & 1) * 16);
    unsigned offT = (unsigned)((wi + (grp & 1) * 8) * SROWB + (grp >> 1) * 16);

    float o[16][4];
#pragma unroll
    for (int j = 0; j < 16; j++)
#pragma unroll
        for (int k = 0; k < 4; k++) o[j][k] = 0.0f;

    auto issue_tile = [&](int t, unsigned bufoff) {
        int q0 = t << 7;
#pragma unroll
        for (int f = tid; f < 2048; f += 256) {
            int r = f >> 4, ch = f & 15;
            CP_ASYNC16(sb + bufoff + r * SROWB + ch * 16,
                       hh + (size_t)(q0 + r) * ND + ch * 8);
        }
        if (tid < 32) CP_ASYNC16(sb + OFF_RQ + ((unsigned)(t & 1) << 9) + tid * 16,
                                 rb + q0 + tid * 4);
        CP_COMMIT();
    };

    issue_tile(0, OFF_HQ0);

    for (int t = 0; t < NT; t++) {
        unsigned bufoff = (t & 1) ? OFF_HQ1 : OFF_HQ0;
        CP_WAIT0();
        __syncthreads();
        if (t + 1 < NT) issue_tile(t + 1, (t & 1) ? OFF_HQ0 : OFF_HQ1);

        int q0 = t << 7;
        const float* s_rq = (const float*)(sm + OFF_RQ + ((unsigned)(t & 1) << 9));

#pragma unroll
        for (int nh = 0; nh < 2; nh++) {
            // combined-scale prefetch: w = rp*rq*ew (independent of S; hides
            // under GEMM1 MMAs and shortens the serial S-process chain)
            float2 eq0[8], eq1[8];
#pragma unroll
            for (int tl = 0; tl < 8; tl++) {
                int col = (nh * 8 + tl) * 8 + 2 * c;
                float2 rq2 = *(const float2*)&s_rq[col];
                float2 e0 = *(const float2*)(ew0 + q0 + col);
                float2 e1 = *(const float2*)(ew1 + q0 + col);
                eq0[tl] = make_float2(rp0 * rq2.x * e0.x, rp0 * rq2.y * e0.y);
                eq1[tl] = make_float2(rp1 * rq2.x * e1.x, rp1 * rq2.y * e1.y);
            }

            // ---- GEMM1: S-half = Hp . Hq^T (single pass) ----
            float s[8][4];
#pragma unroll
            for (int j = 0; j < 8; j++)
#pragma unroll
                for (int k = 0; k < 4; k++) s[j][k] = 0.0f;

#pragma unroll
            for (int kk = 0; kk < 8; kk++) {
                unsigned ah[4];
                ldmx4(ah, sb + OFF_HPH + offA + kk * 32);
                unsigned bh[4][4];
#pragma unroll
                for (int np = 0; np < 4; np++) {
                    unsigned nb = bufoff + (unsigned)((nh * 4 + np) * 16 * SROWB);
                    ldmx4(bh[np], sb + nb + offB + kk * 32);
                }
#pragma unroll
                for (int np = 0; np < 4; np++) {
                    mma_f16(s[2 * np], ah, bh[np][0], bh[np][1]);
                    mma_f16(s[2 * np + 1], ah, bh[np][2], bh[np][3]);
                }
            }

            // ---- scale + pack fp16 -> A fragments ----
            unsigned SAh[4][4];
#pragma unroll
            for (int tl = 0; tl < 8; tl++) {
                float v0 = s[tl][0] * eq0[tl].x;
                float v1 = s[tl][1] * eq0[tl].y;
                float v2 = s[tl][2] * eq1[tl].x;
                float v3 = s[tl][3] * eq1[tl].y;
                int kl = tl >> 1, sl = (tl & 1) * 2;
                SAh[kl][sl]     = pack_f16(v0, v1);
                SAh[kl][sl + 1] = pack_f16(v2, v3);
            }

            // ---- GEMM2 (single pass): o += S x Hq ----
#pragma unroll
            for (int kl = 0; kl < 4; kl++) {
                unsigned kb = bufoff + (unsigned)((nh * 4 + kl) * 16 * SROWB);
#pragma unroll
                for (int npg = 0; npg < 2; npg++) {
                    unsigned bh[4][4];
#pragma unroll
                    for (int np = 0; np < 4; np++)
                        ldmx4t(bh[np], sb + kb + offT + (npg * 4 + np) * 32);
#pragma unroll
                    for (int np = 0; np < 4; np++) {
                        int j = (npg * 4 + np) * 2;
                        mma_f16(o[j], SAh[kl], bh[np][0], bh[np][1]);
                        mma_f16(o[j + 1], SAh[kl], bh[np][2], bh[np][3]);
                    }
                }
            }
        }
    }

    // ================= epilogue =================
    if (is_last) {
        float* ob = dout + (size_t)b * NN * ND;
        float* r0p = ob + (size_t)(p0 + mrow + g) * ND;
        float* r1p = ob + (size_t)(p0 + mrow + g + 8) * ND;
#pragma unroll
        for (int j = 0; j < 16; j++) {
            *(float2*)(r0p + 8 * j + 2 * c) = make_float2(o[j][0], o[j][1]);
            *(float2*)(r1p + 8 * j + 2 * c) = make_float2(o[j][2], o[j][3]);
        }
        return;
    }

    // fused next-layer linear: x = relu(o) -> fp16 split in smem
    __syncthreads();   // all warps done reading HQ buffers
    {
        unsigned r0off = (unsigned)((mrow + g) * SROWB);
        unsigned r1off = (unsigned)((mrow + g + 8) * SROWB);
#pragma unroll
        for (int j = 0; j < 16; j++) {
            unsigned cb = (unsigned)((8 * j + 2 * c) * 2);
            float v0 = fmaxf(o[j][0], 0.f), v1 = fmaxf(o[j][1], 0.f);
            float v2 = fmaxf(o[j][2], 0.f), v3 = fmaxf(o[j][3], 0.f);
            __half h0 = __float2half_rn(v0), h1v = __float2half_rn(v1);
            __half h2 = __float2half_rn(v2), h3v = __float2half_rn(v3);
            *(unsigned*)(sm + OFF_HQ0 + r0off + cb) =
                (unsigned)__half_as_ushort(h0) | ((unsigned)__half_as_ushort(h1v) << 16);
            *(unsigned*)(sm + OFF_HQ1 + r0off + cb) =
                pack_f16(v0 - __half2float(h0), v1 - __half2float(h1v));
            *(unsigned*)(sm + OFF_HQ0 + r1off + cb) =
                (unsigned)__half_as_ushort(h2) | ((unsigned)__half_as_ushort(h3v) << 16);
            *(unsigned*)(sm + OFF_HQ1 + r1off + cb) =
                pack_f16(v2 - __half2float(h2), v3 - __half2float(h3v));
        }
    }
    __syncthreads();

    // h1 = x @ Wn (3-pass fp16 split)
    float o2[16][4];
#pragma unroll
    for (int j = 0; j < 16; j++)
#pragma unroll
        for (int k = 0; k < 4; k++) o2[j][k] = 0.0f;

#pragma unroll
    for (int kl = 0; kl < 8; kl++) {
        unsigned ah[4], al[4];
        ldmx4(ah, sb + OFF_HQ0 + offA + kl * 32);
        ldmx4(al, sb + OFF_HQ1 + offA + kl * 32);
        unsigned kb = (unsigned)(kl * 16 * SROWB);
#pragma unroll
        for (int npg = 0; npg < 2; npg++) {
            unsigned bh[4][4], bl[4][4];
#pragma unroll
            for (int np = 0; np < 4; np++) {
                ldmx4t(bh[np], sb + OFF_WH + offT + kb + (npg * 4 + np) * 32);
                ldmx4t(bl[np], sb + OFF_WL + offT + kb + (npg * 4 + np) * 32);
            }
#pragma unroll
            for (int np = 0; np < 4; np++) {
                int j = (npg * 4 + np) * 2;
                mma_f16(o2[j], ah, bh[np][0], bh[np][1]);
                mma_f16(o2[j + 1], ah, bh[np][2], bh[np][3]);
            }
#pragma unroll
            for (int np = 0; np < 4; np++) {
                int j = (npg * 4 + np) * 2;
                mma_f16(o2[j], al, bh[np][0], bh[np][1]);
                mma_f16(o2[j + 1], al, bh[np][2], bh[np][3]);
            }
#pragma unroll
            for (int np = 0; np < 4; np++) {
                int j = (npg * 4 + np) * 2;
                mma_f16(o2[j], ah, bl[np][0], bl[np][1]);
                mma_f16(o2[j + 1], ah, bl[np][2], bl[np][3]);
            }
        }
    }

    float ss0 = 0.0f, ss1 = 0.0f;
#pragma unroll
    for (int j = 0; j < 16; j++) {
        float2 bv = *(const float2*)(bn + 8 * j + 2 * c);
        o2[j][0] += bv.x; o2[j][1] += bv.y;
        o2[j][2] += bv.x; o2[j][3] += bv.y;
        ss0 += o2[j][0] * o2[j][0] + o2[j][1] * o2[j][1];
        ss1 += o2[j][2] * o2[j][2] + o2[j][3] * o2[j][3];
    }
#pragma unroll
    for (int off = 1; off < 4; off <<= 1) {
        ss0 += __shfl_xor_sync(0xffffffffu, ss0, off);
        ss1 += __shfl_xor_sync(0xffffffffu, ss1, off);
    }
    size_t row0g = (size_t)b * NN + p0 + mrow + g;
    if (c == 0) {
        g_rinv[row0g]     = 1.0f / fmaxf(sqrtf(ss0), 1e-12f);
        g_rinv[row0g + 8] = 1.0f / fmaxf(sqrtf(ss1), 1e-12f);
    }
    unsigned short* d0 = g_h1hi + row0g * ND;
    unsigned short* d1 = g_h1hi + (row0g + 8) * ND;
#pragma unroll
    for (int j = 0; j < 16; j++) {
        *(unsigned*)(d0 + 8 * j + 2 * c) = pack_f16(o2[j][0], o2[j][1]);
        *(unsigned*)(d1 + 8 * j + 2 * c) = pack_f16(o2[j][2], o2[j][3]);
    }
}

// ============================================================
extern "C" void kernel_launch(void* const* d_in, const int* in_sizes, int n_in,
                              void* d_out, int out_size)
{
    const float* x  = (const float*)d_in[0];
    const float* ew = (const float*)d_in[1];
    const float* W0 = (const float*)d_in[2];
    const float* b0 = (const float*)d_in[3];
    const float* W1 = (const float*)d_in[4];
    const float* b1 = (const float*)d_in[5];
    const float* W2 = (const float*)d_in[6];
    const float* b2 = (const float*)d_in[7];
    float* out = (float*)d_out;

    cudaFuncSetAttribute(klinear_mma, cudaFuncAttributeMaxDynamicSharedMemorySize, KL_SMEM);
    cudaFuncSetAttribute(kaggr_fused, cudaFuncAttributeMaxDynamicSharedMemorySize, SM_TOT);

    dim3 gA(NB * NN / 128);
    dim3 gB(NN / 128, NB);

    klinear_mma<<<gA, 256, KL_SMEM>>>(x, W0, b0);
    kaggr_fused<<<gB, 256, SM_TOT>>>(ew, W1, b1, out, 0);
    kaggr_fused<<<gB, 256, SM_TOT>>>(ew, W2, b2, out, 0);
    kaggr_fused<<<gB, 256, SM_TOT>>>(ew, W0, b0, out, 1);
}

// round 17
// speedup vs baseline: 2.2938x; 1.0405x over previous
#include <cuda_runtime.h>
#include <cuda_fp16.h>
#include <math.h>

#define NB 8
#define NN 2048
#define ND 128
#define NT 16

// ---------------- scratch (allocation-free device globals) ----------------
__device__ __align__(16) unsigned short g_h1hi[NB * NN * ND];  // fp16 of h1 [b,n,d]
__device__ __align__(16) float g_rinv[NB * NN];

// ---------------- helpers ----------------
__device__ __forceinline__ unsigned smem_u32(const void* p) {
    unsigned a;
    asm("{ .reg .u64 t; cvta.to.shared.u64 t, %1; cvt.u32.u64 %0, t; }" : "=r"(a) : "l"(p));
    return a;
}
__device__ __forceinline__ void ldmx4(unsigned* r, unsigned a) {
    asm volatile("ldmatrix.sync.aligned.m8n8.x4.shared.b16 {%0,%1,%2,%3}, [%4];"
        : "=r"(r[0]), "=r"(r[1]), "=r"(r[2]), "=r"(r[3]) : "r"(a));
}
__device__ __forceinline__ void ldmx4t(unsigned* r, unsigned a) {
    asm volatile("ldmatrix.sync.aligned.m8n8.x4.trans.shared.b16 {%0,%1,%2,%3}, [%4];"
        : "=r"(r[0]), "=r"(r[1]), "=r"(r[2]), "=r"(r[3]) : "r"(a));
}
__device__ __forceinline__ void mma_f16(float* d, const unsigned* a,
                                        unsigned b0, unsigned b1) {
    asm volatile("mma.sync.aligned.m16n8k16.row.col.f32.f16.f16.f32 "
        "{%0,%1,%2,%3},{%4,%5,%6,%7},{%8,%9},{%0,%1,%2,%3};"
        : "+f"(d[0]), "+f"(d[1]), "+f"(d[2]), "+f"(d[3])
        : "r"(a[0]), "r"(a[1]), "r"(a[2]), "r"(a[3]), "r"(b0), "r"(b1));
}
// pack two f32 -> f16x2 (lo half = first arg)
__device__ __forceinline__ unsigned pack_f16(float lo, float hi) {
    unsigned r;
    asm("cvt.rn.f16x2.f32 %0, %1, %2;" : "=r"(r) : "f"(hi), "f"(lo));
    return r;
}
#define CP_ASYNC16(dst, src) \
    asm volatile("cp.async.cg.shared.global [%0], [%1], 16;" \
        :: "r"((unsigned)(dst)), "l"(src) : "memory")
#define CP_COMMIT() asm volatile("cp.async.commit_group;" ::: "memory")
#define CP_WAIT0()  asm volatile("cp.async.wait_group 0;" ::: "memory")

#define SROWB 272                 // bytes per smem row (128+8 halfs)
#define TILEB 34816               // one 128-row tile

// ---- fp16 hi/lo split of 8 floats -> two uint4 ----
__device__ __forceinline__ void split8(const float* v, uint4* hi4, uint4* lo4) {
    unsigned hi[4], lo[4];
#pragma unroll
    for (int u = 0; u < 4; u++) {
        __half h0 = __float2half_rn(v[2 * u]);
        __half h1 = __float2half_rn(v[2 * u + 1]);
        hi[u] = (unsigned)__half_as_ushort(h0) | ((unsigned)__half_as_ushort(h1) << 16);
        lo[u] = pack_f16(v[2 * u] - __half2float(h0), v[2 * u + 1] - __half2float(h1));
    }
    *hi4 = *(uint4*)hi;
    *lo4 = *(uint4*)lo;
}

// ============================================================
// klinear_mma: h1 = x @ W + b ; rinv = 1/||h1||   (layer 0 only)
// fp16 3-pass split; 128-row tiles, 8 warps.
// ============================================================
#define KL_XH 0
#define KL_XL TILEB
#define KL_WH (2 * TILEB)
#define KL_WL (3 * TILEB)
#define KL_SMEM (4 * TILEB)

__global__ __launch_bounds__(256) void klinear_mma(
    const float* __restrict__ xin, const float* __restrict__ W,
    const float* __restrict__ bias)
{
    extern __shared__ char sm[];
    unsigned sb = smem_u32(sm);
    int tid = threadIdx.x, wid = tid >> 5, lane = tid & 31;
    size_t row0 = (size_t)blockIdx.x * 128;

#pragma unroll
    for (int f = tid; f < 2048; f += 256) {
        int r = f >> 4, ch = f & 15;
        {
            const float* src = xin + (row0 + r) * (size_t)ND + ch * 8;
            float v[8];
#pragma unroll
            for (int u = 0; u < 8; u++) v[u] = src[u];
            split8(v, (uint4*)(sm + KL_XH + r * SROWB + ch * 16),
                      (uint4*)(sm + KL_XL + r * SROWB + ch * 16));
        }
        {
            const float* src = W + (size_t)r * ND + ch * 8;
            float v[8];
#pragma unroll
            for (int u = 0; u < 8; u++) v[u] = src[u];
            split8(v, (uint4*)(sm + KL_WH + r * SROWB + ch * 16),
                      (uint4*)(sm + KL_WL + r * SROWB + ch * 16));
        }
    }
    __syncthreads();

    int g = lane >> 2, c = lane & 3;
    int mrow = wid * 16;
    int grp = lane >> 3, wi = lane & 7;
    unsigned offA = (unsigned)((mrow + wi + (grp & 1) * 8) * SROWB + (grp >> 1) * 16);
    unsigned offT = (unsigned)((wi + (grp & 1) * 8) * SROWB + (grp >> 1) * 16);

    float o[16][4];
#pragma unroll
    for (int j = 0; j < 16; j++)
#pragma unroll
        for (int k = 0; k < 4; k++) o[j][k] = 0.0f;

#pragma unroll
    for (int kl = 0; kl < 8; kl++) {
        unsigned ah[4], al[4];
        ldmx4(ah, sb + KL_XH + offA + kl * 32);
        ldmx4(al, sb + KL_XL + offA + kl * 32);
        unsigned kb = (unsigned)(kl * 16 * SROWB);
#pragma unroll
        for (int npg = 0; npg < 2; npg++) {
            unsigned bh[4][4], bl[4][4];
#pragma unroll
            for (int np = 0; np < 4; np++) {
                ldmx4t(bh[np], sb + KL_WH + offT + kb + (npg * 4 + np) * 32);
                ldmx4t(bl[np], sb + KL_WL + offT + kb + (npg * 4 + np) * 32);
            }
#pragma unroll
            for (int np = 0; np < 4; np++) {
                int j = (npg * 4 + np) * 2;
                mma_f16(o[j], ah, bh[np][0], bh[np][1]);
                mma_f16(o[j + 1], ah, bh[np][2], bh[np][3]);
            }
#pragma unroll
            for (int np = 0; np < 4; np++) {
                int j = (npg * 4 + np) * 2;
                mma_f16(o[j], al, bh[np][0], bh[np][1]);
                mma_f16(o[j + 1], al, bh[np][2], bh[np][3]);
            }
#pragma unroll
            for (int np = 0; np < 4; np++) {
                int j = (npg * 4 + np) * 2;
                mma_f16(o[j], ah, bl[np][0], bl[np][1]);
                mma_f16(o[j + 1], ah, bl[np][2], bl[np][3]);
            }
        }
    }

    float ss0 = 0.0f, ss1 = 0.0f;
#pragma unroll
    for (int j = 0; j < 16; j++) {
        float2 bv = *(const float2*)(bias + 8 * j + 2 * c);
        o[j][0] += bv.x; o[j][1] += bv.y;
        o[j][2] += bv.x; o[j][3] += bv.y;
        ss0 += o[j][0] * o[j][0] + o[j][1] * o[j][1];
        ss1 += o[j][2] * o[j][2] + o[j][3] * o[j][3];
    }
#pragma unroll
    for (int off = 1; off < 4; off <<= 1) {
        ss0 += __shfl_xor_sync(0xffffffffu, ss0, off);
        ss1 += __shfl_xor_sync(0xffffffffu, ss1, off);
    }
    size_t row0g = row0 + mrow + g;
    if (c == 0) {
        g_rinv[row0g]     = 1.0f / fmaxf(sqrtf(ss0), 1e-12f);
        g_rinv[row0g + 8] = 1.0f / fmaxf(sqrtf(ss1), 1e-12f);
    }
    unsigned short* d0 = g_h1hi + row0g * ND;
    unsigned short* d1 = g_h1hi + (row0g + 8) * ND;
#pragma unroll
    for (int j = 0; j < 16; j++) {
        *(unsigned*)(d0 + 8 * j + 2 * c) = pack_f16(o[j][0], o[j][1]);
        *(unsigned*)(d1 + 8 * j + 2 * c) = pack_f16(o[j][2], o[j][3]);
    }
}

// ============================================================
// kaggr_fused: aggregation (single-pass fp16 MMA, software-pipelined
// fragment loads) + fused next-layer linear in epilogue.
// ============================================================
#define OFF_HPH 0
#define OFF_HQ0 TILEB             // q-tile buffer 0 / epilogue x_hi
#define OFF_HQ1 (2 * TILEB)       // q-tile buffer 1 / epilogue x_lo
#define OFF_WH  (3 * TILEB)
#define OFF_WL  (4 * TILEB)
#define OFF_RQ  (5 * TILEB)       // 2 x 512B
#define SM_TOT  (5 * TILEB + 1024)

__global__ __launch_bounds__(256) void kaggr_fused(
    const float* __restrict__ ew, const float* __restrict__ Wn,
    const float* __restrict__ bn, float* __restrict__ dout, int is_last)
{
    extern __shared__ char sm[];
    unsigned sb = smem_u32(sm);
    int tid = threadIdx.x, wid = tid >> 5, lane = tid & 31;
    int b = blockIdx.y, p0 = blockIdx.x * 128;

    const unsigned short* hh = g_h1hi + (size_t)b * NN * ND;
    const float* ewb = ew + (size_t)b * NN * NN;
    const float* rb = g_rinv + (size_t)b * NN;

    // persistent Hp tile (+ W conversion for the fused linear)
#pragma unroll
    for (int f = tid; f < 2048; f += 256) {
        int r = f >> 4, ch = f & 15;
        *(uint4*)(sm + OFF_HPH + r * SROWB + ch * 16) =
            *(const uint4*)(hh + (size_t)(p0 + r) * ND + ch * 8);
        if (!is_last) {
            const float* src = Wn + (size_t)r * ND + ch * 8;
            float v[8];
#pragma unroll
            for (int u = 0; u < 8; u++) v[u] = src[u];
            split8(v, (uint4*)(sm + OFF_WH + r * SROWB + ch * 16),
                      (uint4*)(sm + OFF_WL + r * SROWB + ch * 16));
        }
    }

    int g = lane >> 2, c = lane & 3;
    int mrow = wid * 16;
    float rp0 = rb[p0 + mrow + g];
    float rp1 = rb[p0 + mrow + g + 8];
    const float* ew0 = ewb + (size_t)(p0 + mrow + g) * NN;
    const float* ew1 = ewb + (size_t)(p0 + mrow + g + 8) * NN;

    int grp = lane >> 3, wi = lane & 7;
    unsigned offA = (unsigned)((mrow + wi + (grp & 1) * 8) * SROWB + (grp >> 1) * 16);
    unsigned offB = (unsigned)((wi + (grp >> 1) * 8) * SROWB + (grp & 1) * 16);
    unsigned offT = (unsigned)((wi + (grp & 1) * 8) * SROWB + (grp >> 1) * 16);

    float o[16][4];
#pragma unroll
    for (int j = 0; j < 16; j++)
#pragma unroll
        for (int k = 0; k < 4; k++) o[j][k] = 0.0f;

    auto issue_tile = [&](int t, unsigned bufoff) {
        int q0 = t << 7;
#pragma unroll
        for (int f = tid; f < 2048; f += 256) {
            int r = f >> 4, ch = f & 15;
            CP_ASYNC16(sb + bufoff + r * SROWB + ch * 16,
                       hh + (size_t)(q0 + r) * ND + ch * 8);
        }
        if (tid < 32) CP_ASYNC16(sb + OFF_RQ + ((unsigned)(t & 1) << 9) + tid * 16,
                                 rb + q0 + tid * 4);
        CP_COMMIT();
    };

    issue_tile(0, OFF_HQ0);

    for (int t = 0; t < NT; t++) {
        unsigned bufoff = (t & 1) ? OFF_HQ1 : OFF_HQ0;
        CP_WAIT0();
        __syncthreads();
        if (t + 1 < NT) issue_tile(t + 1, (t & 1) ? OFF_HQ0 : OFF_HQ1);

        int q0 = t << 7;
        const float* s_rq = (const float*)(sm + OFF_RQ + ((unsigned)(t & 1) << 9));

#pragma unroll
        for (int nh = 0; nh < 2; nh++) {
            // combined-scale prefetch: w = rp*rq*ew (hidden under GEMM1 MMAs)
            float2 eq0[8], eq1[8];
#pragma unroll
            for (int tl = 0; tl < 8; tl++) {
                int col = (nh * 8 + tl) * 8 + 2 * c;
                float2 rq2 = *(const float2*)&s_rq[col];
                float2 e0 = *(const float2*)(ew0 + q0 + col);
                float2 e1 = *(const float2*)(ew1 + q0 + col);
                eq0[tl] = make_float2(rp0 * rq2.x * e0.x, rp0 * rq2.y * e0.y);
                eq1[tl] = make_float2(rp1 * rq2.x * e1.x, rp1 * rq2.y * e1.y);
            }

            // ---- GEMM1: S-half = Hp . Hq^T, double-buffered fragments ----
            float s[8][4];
#pragma unroll
            for (int j = 0; j < 8; j++)
#pragma unroll
                for (int k = 0; k < 4; k++) s[j][k] = 0.0f;

            unsigned nbase = bufoff + (unsigned)(nh * 4 * 16 * SROWB);
            unsigned ah[2][4], bh[2][4][4];
            ldmx4(ah[0], sb + OFF_HPH + offA);
#pragma unroll
            for (int np = 0; np < 4; np++)
                ldmx4(bh[0][np], sb + nbase + (unsigned)(np * 16 * SROWB) + offB);

#pragma unroll
            for (int kk = 0; kk < 8; kk++) {
                int cur = kk & 1, nxt = cur ^ 1;
                if (kk < 7) {
                    ldmx4(ah[nxt], sb + OFF_HPH + offA + (kk + 1) * 32);
#pragma unroll
                    for (int np = 0; np < 4; np++)
                        ldmx4(bh[nxt][np],
                              sb + nbase + (unsigned)(np * 16 * SROWB) + offB + (kk + 1) * 32);
                }
#pragma unroll
                for (int np = 0; np < 4; np++) {
                    mma_f16(s[2 * np], ah[cur], bh[cur][np][0], bh[cur][np][1]);
                    mma_f16(s[2 * np + 1], ah[cur], bh[cur][np][2], bh[cur][np][3]);
                }
            }

            // ---- scale + pack fp16 -> A fragments ----
            unsigned SAh[4][4];
#pragma unroll
            for (int tl = 0; tl < 8; tl++) {
                float v0 = s[tl][0] * eq0[tl].x;
                float v1 = s[tl][1] * eq0[tl].y;
                float v2 = s[tl][2] * eq1[tl].x;
                float v3 = s[tl][3] * eq1[tl].y;
                int kl = tl >> 1, sl = (tl & 1) * 2;
                SAh[kl][sl]     = pack_f16(v0, v1);
                SAh[kl][sl + 1] = pack_f16(v2, v3);
            }

            // ---- GEMM2: o += S x Hq, double-buffered B fragments ----
            unsigned bt[2][4][4];
#pragma unroll
            for (int np = 0; np < 4; np++)
                ldmx4t(bt[0][np], sb + nbase + offT + np * 32);

#pragma unroll
            for (int gi = 0; gi < 8; gi++) {
                int cur = gi & 1, nxt = cur ^ 1;
                if (gi < 7) {
                    int gn = gi + 1;
                    unsigned kbn = nbase + (unsigned)((gn >> 1) * 16 * SROWB);
#pragma unroll
                    for (int np = 0; np < 4; np++)
                        ldmx4t(bt[nxt][np], sb + kbn + offT + ((gn & 1) * 4 + np) * 32);
                }
                int kl = gi >> 1, npg = gi & 1;
#pragma unroll
                for (int np = 0; np < 4; np++) {
                    int j = (npg * 4 + np) * 2;
                    mma_f16(o[j], SAh[kl], bt[cur][np][0], bt[cur][np][1]);
                    mma_f16(o[j + 1], SAh[kl], bt[cur][np][2], bt[cur][np][3]);
                }
            }
        }
    }

    // ================= epilogue =================
    if (is_last) {
        float* ob = dout + (size_t)b * NN * ND;
        float* r0p = ob + (size_t)(p0 + mrow + g) * ND;
        float* r1p = ob + (size_t)(p0 + mrow + g + 8) * ND;
#pragma unroll
        for (int j = 0; j < 16; j++) {
            *(float2*)(r0p + 8 * j + 2 * c) = make_float2(o[j][0], o[j][1]);
            *(float2*)(r1p + 8 * j + 2 * c) = make_float2(o[j][2], o[j][3]);
        }
        return;
    }

    // fused next-layer linear: x = relu(o) -> fp16 split in smem
    __syncthreads();   // all warps done reading HQ buffers
    {
        unsigned r0off = (unsigned)((mrow + g) * SROWB);
        unsigned r1off = (unsigned)((mrow + g + 8) * SROWB);
#pragma unroll
        for (int j = 0; j < 16; j++) {
            unsigned cb = (unsigned)((8 * j + 2 * c) * 2);
            float v0 = fmaxf(o[j][0], 0.f), v1 = fmaxf(o[j][1], 0.f);
            float v2 = fmaxf(o[j][2], 0.f), v3 = fmaxf(o[j][3], 0.f);
            __half h0 = __float2half_rn(v0), h1v = __float2half_rn(v1);
            __half h2 = __float2half_rn(v2), h3v = __float2half_rn(v3);
            *(unsigned*)(sm + OFF_HQ0 + r0off + cb) =
                (unsigned)__half_as_ushort(h0) | ((unsigned)__half_as_ushort(h1v) << 16);
            *(unsigned*)(sm + OFF_HQ1 + r0off + cb) =
                pack_f16(v0 - __half2float(h0), v1 - __half2float(h1v));
            *(unsigned*)(sm + OFF_HQ0 + r1off + cb) =
                (unsigned)__half_as_ushort(h2) | ((unsigned)__half_as_ushort(h3v) << 16);
            *(unsigned*)(sm + OFF_HQ1 + r1off + cb) =
                pack_f16(v2 - __half2float(h2), v3 - __half2float(h3v));
        }
    }
    __syncthreads();

    // h1 = x @ Wn (3-pass fp16 split)
    float o2[16][4];
#pragma unroll
    for (int j = 0; j < 16; j++)
#pragma unroll
        for (int k = 0; k < 4; k++) o2[j][k] = 0.0f;

#pragma unroll
    for (int kl = 0; kl < 8; kl++) {
        unsigned ah[4], al[4];
        ldmx4(ah, sb + OFF_HQ0 + offA + kl * 32);
        ldmx4(al, sb + OFF_HQ1 + offA + kl * 32);
        unsigned kb = (unsigned)(kl * 16 * SROWB);
#pragma unroll
        for (int npg = 0; npg < 2; npg++) {
            unsigned bh[4][4], bl[4][4];
#pragma unroll
            for (int np = 0; np < 4; np++) {
                ldmx4t(bh[np], sb + OFF_WH + offT + kb + (npg * 4 + np) * 32);
                ldmx4t(bl[np], sb + OFF_WL + offT + kb + (npg * 4 + np) * 32);
            }
#pragma unroll
            for (int np = 0; np < 4; np++) {
                int j = (npg * 4 + np) * 2;
                mma_f16(o2[j], ah, bh[np][0], bh[np][1]);
                mma_f16(o2[j + 1], ah, bh[np][2], bh[np][3]);
            }
#pragma unroll
            for (int np = 0; np < 4; np++) {
                int j = (npg * 4 + np) * 2;
                mma_f16(o2[j], al, bh[np][0], bh[np][1]);
                mma_f16(o2[j + 1], al, bh[np][2], bh[np][3]);
            }
#pragma unroll
            for (int np = 0; np < 4; np++) {
                int j = (npg * 4 + np) * 2;
                mma_f16(o2[j], ah, bl[np][0], bl[np][1]);
                mma_f16(o2[j + 1], ah, bl[np][2], bl[np][3]);
            }
        }
    }

    float ss0 = 0.0f, ss1 = 0.0f;
#pragma unroll
    for (int j = 0; j < 16; j++) {
        float2 bv = *(const float2*)(bn + 8 * j + 2 * c);
        o2[j][0] += bv.x; o2[j][1] += bv.y;
        o2[j][2] += bv.x; o2[j][3] += bv.y;
        ss0 += o2[j][0] * o2[j][0] + o2[j][1] * o2[j][1];
        ss1 += o2[j][2] * o2[j][2] + o2[j][3] * o2[j][3];
    }
#pragma unroll
    for (int off = 1; off < 4; off <<= 1) {
        ss0 += __shfl_xor_sync(0xffffffffu, ss0, off);
        ss1 += __shfl_xor_sync(0xffffffffu, ss1, off);
    }
    size_t row0g = (size_t)b * NN + p0 + mrow + g;
    if (c == 0) {
        g_rinv[row0g]     = 1.0f / fmaxf(sqrtf(ss0), 1e-12f);
        g_rinv[row0g + 8] = 1.0f / fmaxf(sqrtf(ss1), 1e-12f);
    }
    unsigned short* d0 = g_h1hi + row0g * ND;
    unsigned short* d1 = g_h1hi + (row0g + 8) * ND;
#pragma unroll
    for (int j = 0; j < 16; j++) {
        *(unsigned*)(d0 + 8 * j + 2 * c) = pack_f16(o2[j][0], o2[j][1]);
        *(unsigned*)(d1 + 8 * j + 2 * c) = pack_f16(o2[j][2], o2[j][3]);
    }
}

// ============================================================
extern "C" void kernel_launch(void* const* d_in, const int* in_sizes, int n_in,
                              void* d_out, int out_size)
{
    const float* x  = (const float*)d_in[0];
    const float* ew = (const float*)d_in[1];
    const float* W0 = (const float*)d_in[2];
    const float* b0 = (const float*)d_in[3];
    const float* W1 = (const float*)d_in[4];
    const float* b1 = (const float*)d_in[5];
    const float* W2 = (const float*)d_in[6];
    const float* b2 = (const float*)d_in[7];
    float* out = (float*)d_out;

    cudaFuncSetAttribute(klinear_mma, cudaFuncAttributeMaxDynamicSharedMemorySize, KL_SMEM);
    cudaFuncSetAttribute(kaggr_fused, cudaFuncAttributeMaxDynamicSharedMemorySize, SM_TOT);

    dim3 gA(NB * NN / 128);
    dim3 gB(NN / 128, NB);

    klinear_mma<<<gA, 256, KL_SMEM>>>(x, W0, b0);
    kaggr_fused<<<gB, 256, SM_TOT>>>(ew, W1, b1, out, 0);
    kaggr_fused<<<gB, 256, SM_TOT>>>(ew, W2, b2, out, 0);
    kaggr_fused<<<gB, 256, SM_TOT>>>(ew, W0, b0, out, 1);
}